// round 5
// baseline (speedup 1.0000x reference)
#include <cuda_runtime.h>
#include <cuda_bf16.h>
#include <cstdint>

#define HIDDEN 2048
#define SEQ    2048
#define BATCH  2
#define NHEADS 16
#define HDIM   128
#define MROWS  (BATCH * SEQ)   // 4096

typedef unsigned long long ull;

// ---------- f32x2 packed-math helpers ----------
__device__ __forceinline__ ull fpack2(float lo, float hi) {
    ull r; asm("mov.b64 %0, {%1,%2};" : "=l"(r) : "f"(lo), "f"(hi)); return r;
}
__device__ __forceinline__ ull fdup2(float v) { return fpack2(v, v); }
__device__ __forceinline__ float2 funpack2(ull v) {
    float2 r; asm("mov.b64 {%0,%1}, %2;" : "=f"(r.x), "=f"(r.y) : "l"(v)); return r;
}
__device__ __forceinline__ ull ffma2(ull a, ull b, ull c) {
    ull d; asm("fma.rn.f32x2 %0, %1, %2, %3;" : "=l"(d) : "l"(a), "l"(b), "l"(c)); return d;
}
__device__ __forceinline__ ull fmul2_(ull a, ull b) {
    ull d; asm("mul.rn.f32x2 %0, %1, %2;" : "=l"(d) : "l"(a), "l"(b)); return d;
}

// ---------- scratch ----------
__device__ float g_Q[MROWS * HIDDEN];
__device__ float g_K[MROWS * HIDDEN];
__device__ float g_V[MROWS * HIDDEN];
__device__ __nv_bfloat16 g_xh[MROWS * HIDDEN], g_xl[MROWS * HIDDEN];
__device__ __nv_bfloat16 g_oh[MROWS * HIDDEN], g_ol[MROWS * HIDDEN];
__device__ __nv_bfloat16 g_wqh[HIDDEN * HIDDEN], g_wql[HIDDEN * HIDDEN];
__device__ __nv_bfloat16 g_wkh[HIDDEN * HIDDEN], g_wkl[HIDDEN * HIDDEN];
__device__ __nv_bfloat16 g_wvh[HIDDEN * HIDDEN], g_wvl[HIDDEN * HIDDEN];
__device__ __nv_bfloat16 g_woh[HIDDEN * HIDDEN], g_wol[HIDDEN * HIDDEN];

// ---------- PTX wrappers (sm_80-era, valid on compute_103) ----------
__device__ __forceinline__ uint32_t smem_u32(const void* p) {
    uint32_t a;
    asm("{ .reg .u64 t; cvta.to.shared.u64 t, %1; cvt.u32.u64 %0, t; }" : "=r"(a) : "l"(p));
    return a;
}
__device__ __forceinline__ void cp16(uint32_t sdst, const void* gsrc) {
    asm volatile("cp.async.cg.shared.global [%0], [%1], 16;" :: "r"(sdst), "l"(gsrc) : "memory");
}
#define CP_COMMIT() asm volatile("cp.async.commit_group;" ::: "memory")
#define CP_WAIT1()  asm volatile("cp.async.wait_group 1;" ::: "memory")

__device__ __forceinline__ void ldsm_x4(uint32_t (&r)[4], uint32_t addr) {
    asm volatile("ldmatrix.sync.aligned.m8n8.x4.shared.b16 {%0,%1,%2,%3}, [%4];"
                 : "=r"(r[0]), "=r"(r[1]), "=r"(r[2]), "=r"(r[3]) : "r"(addr));
}
__device__ __forceinline__ void mma16816(float (&d)[4], const uint32_t (&a)[4],
                                         uint32_t b0, uint32_t b1) {
    asm volatile(
        "mma.sync.aligned.m16n8k16.row.col.f32.bf16.bf16.f32 "
        "{%0,%1,%2,%3}, {%4,%5,%6,%7}, {%8,%9}, {%0,%1,%2,%3};"
        : "+f"(d[0]), "+f"(d[1]), "+f"(d[2]), "+f"(d[3])
        : "r"(a[0]), "r"(a[1]), "r"(a[2]), "r"(a[3]), "r"(b0), "r"(b1));
}

// ---------- fused fp32 -> bf16 hi/lo split for all 5 inputs ----------
__global__ __launch_bounds__(256)
void cvt_all(const float4* __restrict__ x,  const float4* __restrict__ wq,
             const float4* __restrict__ wk, const float4* __restrict__ wv,
             const float4* __restrict__ wo,
             __nv_bfloat162* xh,  __nv_bfloat162* xl,
             __nv_bfloat162* wqh, __nv_bfloat162* wql,
             __nv_bfloat162* wkh, __nv_bfloat162* wkl,
             __nv_bfloat162* wvh, __nv_bfloat162* wvl,
             __nv_bfloat162* woh, __nv_bfloat162* wol)
{
    int bid = blockIdx.x;
    const float4* src; __nv_bfloat162 *ph, *pl; int base;
    if      (bid <  8192) { src = x;  ph = xh;  pl = xl;  base = bid; }
    else if (bid < 12288) { src = wq; ph = wqh; pl = wql; base = bid - 8192; }
    else if (bid < 16384) { src = wk; ph = wkh; pl = wkl; base = bid - 12288; }
    else if (bid < 20480) { src = wv; ph = wvh; pl = wvl; base = bid - 16384; }
    else                  { src = wo; ph = woh; pl = wol; base = bid - 20480; }
    size_t i = (size_t)base * 256 + threadIdx.x;
    float4 v = src[i];
    __nv_bfloat16 hx = __float2bfloat16(v.x);
    __nv_bfloat16 hy = __float2bfloat16(v.y);
    __nv_bfloat16 hz = __float2bfloat16(v.z);
    __nv_bfloat16 hw = __float2bfloat16(v.w);
    ph[2 * i]     = __halves2bfloat162(hx, hy);
    ph[2 * i + 1] = __halves2bfloat162(hz, hw);
    pl[2 * i]     = __halves2bfloat162(__float2bfloat16(v.x - __bfloat162float(hx)),
                                       __float2bfloat16(v.y - __bfloat162float(hy)));
    pl[2 * i + 1] = __halves2bfloat162(__float2bfloat16(v.z - __bfloat162float(hz)),
                                       __float2bfloat16(v.w - __bfloat162float(hw)));
}

// =====================================================================
// HMMA GEMM: 128x128 CTA tile, 8 warps (4m x 2n), BK=32, 80B rows.
// 2-stage cp.async pipeline, 80KB smem/CTA -> 2 CTAs/SM (16 warps/SM).
// Passes: Ah*Bh | Al*Bh | Ah*Bl (bl loaded per-np to cap registers).
// =====================================================================
#define BK       32
#define NKCH     (HIDDEN / BK)          // 64
#define ROWB     80
#define TILE_B   (128 * ROWB)           // 10240
#define STAGE_B  (4 * TILE_B)           // 40960: Ah Al Bh Bl
#define NSTAGE   2
#define GEMM_SMEM (NSTAGE * STAGE_B)    // 81920

__global__ __launch_bounds__(256, 2)
void gemm_mma(const __nv_bfloat16* __restrict__ Ah, const __nv_bfloat16* __restrict__ Al,
              const __nv_bfloat16* __restrict__ Bh, const __nv_bfloat16* __restrict__ Bl,
              float* __restrict__ C, int M, int N, int K)
{
    extern __shared__ __align__(128) char smem[];
    const uint32_t sbase = smem_u32(smem);
    const int tid  = threadIdx.x;
    const int wid  = tid >> 5;
    const int lane = tid & 31;
    const int wm   = wid & 3;
    const int wn   = wid >> 2;
    const size_t brow = (size_t)blockIdx.y * 128;
    const size_t bcol = (size_t)blockIdx.x * 128;

    const int row  = tid >> 1;
    const int segq = (tid & 1) * 2;
    const uint32_t soff0 = (uint32_t)(row * ROWB + segq * 16);
    const uint32_t soff1 = soff0 + 16;

    const size_t Kb = (size_t)K * 2;
    const char* pAh = (const char*)Ah + (brow + row) * Kb + segq * 16;
    const char* pAl = (const char*)Al + (brow + row) * Kb + segq * 16;
    const char* pBh = (const char*)Bh + (bcol + row) * Kb + segq * 16;
    const char* pBl = (const char*)Bl + (bcol + row) * Kb + segq * 16;

#define LOAD_CHUNK(c, s) do {                                    \
        uint32_t sb_ = sbase + (uint32_t)(s) * STAGE_B;          \
        size_t g_ = (size_t)(c) * 64;                            \
        cp16(sb_ + 0 * TILE_B + soff0, pAh + g_);                \
        cp16(sb_ + 0 * TILE_B + soff1, pAh + g_ + 16);           \
        cp16(sb_ + 1 * TILE_B + soff0, pAl + g_);                \
        cp16(sb_ + 1 * TILE_B + soff1, pAl + g_ + 16);           \
        cp16(sb_ + 2 * TILE_B + soff0, pBh + g_);                \
        cp16(sb_ + 2 * TILE_B + soff1, pBh + g_ + 16);           \
        cp16(sb_ + 3 * TILE_B + soff0, pBl + g_);                \
        cp16(sb_ + 3 * TILE_B + soff1, pBl + g_ + 16);           \
    } while (0)

    const int rA   = wm * 32 + (lane & 15);
    const int aSeg = lane >> 4;
    const int rB   = wn * 64 + ((lane >> 4) << 3) + (lane & 7);
    const int bSeg = (lane >> 3) & 1;

    float acc[2][8][4];
#pragma unroll
    for (int mt = 0; mt < 2; ++mt)
#pragma unroll
        for (int nt = 0; nt < 8; ++nt)
#pragma unroll
            for (int q = 0; q < 4; ++q) acc[mt][nt][q] = 0.f;

    LOAD_CHUNK(0, 0); CP_COMMIT();
    LOAD_CHUNK(1, 1); CP_COMMIT();

    for (int c = 0; c < NKCH; ++c) {
        CP_WAIT1();           // chunk c's data complete
        __syncthreads();      // visible to all warps

        const uint32_t sb = sbase + (uint32_t)(c & 1) * STAGE_B;

#pragma unroll
        for (int k16 = 0; k16 < 2; ++k16) {
            uint32_t ah[2][4], al[2][4];
#pragma unroll
            for (int mt = 0; mt < 2; ++mt) {
                uint32_t byteoff = (uint32_t)((rA + mt * 16) * ROWB + (2 * k16 + aSeg) * 16);
                ldsm_x4(ah[mt], sb + 0 * TILE_B + byteoff);
                ldsm_x4(al[mt], sb + 1 * TILE_B + byteoff);
            }
            uint32_t bh[4][4];
#pragma unroll
            for (int np = 0; np < 4; ++np) {
                uint32_t byteoff = (uint32_t)((rB + np * 16) * ROWB + (2 * k16 + bSeg) * 16);
                ldsm_x4(bh[np], sb + 2 * TILE_B + byteoff);
            }
            // pass 1: Ah * Bh
#pragma unroll
            for (int np = 0; np < 4; ++np)
#pragma unroll
                for (int mt = 0; mt < 2; ++mt) {
                    mma16816(acc[mt][2 * np + 0], ah[mt], bh[np][0], bh[np][1]);
                    mma16816(acc[mt][2 * np + 1], ah[mt], bh[np][2], bh[np][3]);
                }
            // pass 2: Al * Bh
#pragma unroll
            for (int np = 0; np < 4; ++np)
#pragma unroll
                for (int mt = 0; mt < 2; ++mt) {
                    mma16816(acc[mt][2 * np + 0], al[mt], bh[np][0], bh[np][1]);
                    mma16816(acc[mt][2 * np + 1], al[mt], bh[np][2], bh[np][3]);
                }
            // pass 3: Ah * Bl (bl loaded per-np; caps register count)
#pragma unroll
            for (int np = 0; np < 4; ++np) {
                uint32_t byteoff = (uint32_t)((rB + np * 16) * ROWB + (2 * k16 + bSeg) * 16);
                uint32_t bl[4];
                ldsm_x4(bl, sb + 3 * TILE_B + byteoff);
#pragma unroll
                for (int mt = 0; mt < 2; ++mt) {
                    mma16816(acc[mt][2 * np + 0], ah[mt], bl[0], bl[1]);
                    mma16816(acc[mt][2 * np + 1], ah[mt], bl[2], bl[3]);
                }
            }
        }

        __syncthreads();      // all warps done reading stage (c&1)
        if (c + 2 < NKCH) LOAD_CHUNK(c + 2, c & 1);
        CP_COMMIT();
    }

#pragma unroll
    for (int mt = 0; mt < 2; ++mt) {
        size_t r0 = brow + wm * 32 + mt * 16 + (lane >> 2);
#pragma unroll
        for (int nt = 0; nt < 8; ++nt) {
            size_t col = bcol + wn * 64 + nt * 8 + 2 * (lane & 3);
            *(float2*)&C[r0 * (size_t)N + col]       = make_float2(acc[mt][nt][0], acc[mt][nt][1]);
            *(float2*)&C[(r0 + 8) * (size_t)N + col] = make_float2(acc[mt][nt][2], acc[mt][nt][3]);
        }
    }
}

// =====================================================================
// Flash attention, 512 threads/CTA (2 q-rows per thread), f32x2 core.
// smem: Qs[64][128] | Kt[64][130] | Vt[128][66] | Ps[64][80]
// =====================================================================
#define ATTN_SMEM_FLOATS (8192 + 8320 + 8448 + 5120)
#define ATTN_SMEM_BYTES  (ATTN_SMEM_FLOATS * 4)

__global__ __launch_bounds__(512, 1)
void attn_kernel(const float* __restrict__ Q, const float* __restrict__ K,
                 const float* __restrict__ V,
                 __nv_bfloat16* __restrict__ Oh, __nv_bfloat16* __restrict__ Ol)
{
    extern __shared__ __align__(16) float sm[];
    float* Qs = sm;                 // [64][128]
    float* Kt = sm + 8192;          // [64][130]
    float* Vt = sm + 16512;         // [128][66]
    float* Ps = sm + 24960;         // [64][80]

    const int tid = threadIdx.x;
    const int tx  = tid & 15;
    const int ty  = tid >> 4;       // 0..31
    const int b   = blockIdx.x >> 4;
    const int h   = blockIdx.x & 15;
    const int qt  = blockIdx.y;

    const float scale = 0.08838834764831843f;
    const size_t base = ((size_t)b * SEQ) * HIDDEN + (size_t)h * HDIM;

    // ---- load Q tile (scaled): 2048 float4, 4 iters of 512 ----
#pragma unroll
    for (int it = 0; it < 4; ++it) {
        int idx = it * 512 + tid;
        int r   = idx >> 5;
        int c4  = (idx & 31) << 2;
        float4 v = *(const float4*)(Q + base + (size_t)(qt * 64 + r) * HIDDEN + c4);
        v.x *= scale; v.y *= scale; v.z *= scale; v.w *= scale;
        *(float4*)&Qs[r * 128 + c4] = v;
    }

    ull   O2[2][8];
    float m_i[2], l_i[2];
#pragma unroll
    for (int i = 0; i < 2; ++i) {
        m_i[i] = -3.402823466e38f;
        l_i[i] = 0.f;
#pragma unroll
        for (int j = 0; j < 8; ++j) O2[i][j] = 0ull;
    }

    for (int kt = 0; kt < SEQ / 64; ++kt) {
        __syncthreads();
        const float* Kg = K + base + (size_t)(kt * 64) * HIDDEN;
        const float* Vg = V + base + (size_t)(kt * 64) * HIDDEN;
#pragma unroll
        for (int it = 0; it < 8; ++it) {
            int idx = it * 512 + tid;       // float2 index, 64*64
            int r   = idx >> 6;
            int c2  = idx & 63;
            float2 kv = *(const float2*)(Kg + (size_t)r * HIDDEN + c2 * 2);
            *(float2*)&Kt[r * 130 + c2 * 2] = kv;
            float2 vv = *(const float2*)(Vg + (size_t)r * HIDDEN + c2 * 2);
            Vt[(c2 * 2    ) * 66 + r] = vv.x;
            Vt[(c2 * 2 + 1) * 66 + r] = vv.y;
        }
        __syncthreads();

        // ---- scores ----
        ull s2[2][4];
#pragma unroll
        for (int i = 0; i < 2; ++i)
#pragma unroll
            for (int j = 0; j < 4; ++j) s2[i][j] = 0ull;

#pragma unroll 4
        for (int d2 = 0; d2 < 64; ++d2) {
            ull q2[2], k2[4];
#pragma unroll
            for (int i = 0; i < 2; ++i)
                q2[i] = *(const ull*)&Qs[(ty * 2 + i) * 128 + d2 * 2];
#pragma unroll
            for (int j = 0; j < 4; ++j)
                k2[j] = *(const ull*)&Kt[(tx + 16 * j) * 130 + d2 * 2];
#pragma unroll
            for (int i = 0; i < 2; ++i)
#pragma unroll
                for (int j = 0; j < 4; ++j)
                    s2[i][j] = ffma2(q2[i], k2[j], s2[i][j]);
        }

        // ---- online softmax ----
#pragma unroll
        for (int i = 0; i < 2; ++i) {
            float s[4];
            float rmax = -3.402823466e38f;
#pragma unroll
            for (int j = 0; j < 4; ++j) {
                float2 f = funpack2(s2[i][j]);
                s[j] = f.x + f.y;
                rmax = fmaxf(rmax, s[j]);
            }
#pragma unroll
            for (int off = 8; off; off >>= 1)
                rmax = fmaxf(rmax, __shfl_xor_sync(0xffffffffu, rmax, off));
            float mnew = fmaxf(m_i[i], rmax);
            float c = __expf(m_i[i] - mnew);
            m_i[i] = mnew;
            float rsum = 0.f;
#pragma unroll
            for (int j = 0; j < 4; ++j) {
                float p = __expf(s[j] - mnew);
                rsum += p;
                Ps[(ty * 2 + i) * 80 + tx + 16 * j] = p;
            }
#pragma unroll
            for (int off = 8; off; off >>= 1)
                rsum += __shfl_xor_sync(0xffffffffu, rsum, off);
            l_i[i] = l_i[i] * c + rsum;
            ull cd = fdup2(c);
#pragma unroll
            for (int j = 0; j < 8; ++j) O2[i][j] = fmul2_(O2[i][j], cd);
        }
        __syncthreads();

        // ---- O += P @ V ----
#pragma unroll 2
        for (int kk = 0; kk < 32; ++kk) {
            ull p2[2], v2[8];
#pragma unroll
            for (int i = 0; i < 2; ++i)
                p2[i] = *(const ull*)&Ps[(ty * 2 + i) * 80 + kk * 2];
#pragma unroll
            for (int j = 0; j < 8; ++j)
                v2[j] = *(const ull*)&Vt[(tx + 16 * j) * 66 + kk * 2];
#pragma unroll
            for (int i = 0; i < 2; ++i)
#pragma unroll
                for (int j = 0; j < 8; ++j)
                    O2[i][j] = ffma2(p2[i], v2[j], O2[i][j]);
        }
    }

    // ---- epilogue: fold pairs, normalize, bf16 hi/lo ----
#pragma unroll
    for (int i = 0; i < 2; ++i) {
        float inv = 1.0f / l_i[i];
        size_t rowo = base + (size_t)(qt * 64 + ty * 2 + i) * HIDDEN;
#pragma unroll
        for (int j = 0; j < 8; ++j) {
            float2 f = funpack2(O2[i][j]);
            float o = (f.x + f.y) * inv;
            __nv_bfloat16 hb = __float2bfloat16(o);
            Oh[rowo + tx + 16 * j] = hb;
            Ol[rowo + tx + 16 * j] = __float2bfloat16(o - __bfloat162float(hb));
        }
    }
}

// =====================================================================
extern "C" void kernel_launch(void* const* d_in, const int* in_sizes, int n_in,
                              void* d_out, int out_size)
{
    const float* x  = (const float*)d_in[0];
    const float* wq = (const float*)d_in[1];
    const float* wk = (const float*)d_in[2];
    const float* wv = (const float*)d_in[3];
    const float* wo = (const float*)d_in[4];
    float* out = (float*)d_out;

    float *Qp, *Kp, *Vp;
    cudaGetSymbolAddress((void**)&Qp, g_Q);
    cudaGetSymbolAddress((void**)&Kp, g_K);
    cudaGetSymbolAddress((void**)&Vp, g_V);
    __nv_bfloat16 *xh, *xl, *oh, *ol;
    __nv_bfloat16 *wqh, *wql, *wkh, *wkl, *wvh, *wvl, *woh, *wol;
    cudaGetSymbolAddress((void**)&xh, g_xh);  cudaGetSymbolAddress((void**)&xl, g_xl);
    cudaGetSymbolAddress((void**)&oh, g_oh);  cudaGetSymbolAddress((void**)&ol, g_ol);
    cudaGetSymbolAddress((void**)&wqh, g_wqh); cudaGetSymbolAddress((void**)&wql, g_wql);
    cudaGetSymbolAddress((void**)&wkh, g_wkh); cudaGetSymbolAddress((void**)&wkl, g_wkl);
    cudaGetSymbolAddress((void**)&wvh, g_wvh); cudaGetSymbolAddress((void**)&wvl, g_wvl);
    cudaGetSymbolAddress((void**)&woh, g_woh); cudaGetSymbolAddress((void**)&wol, g_wol);

    const int M = MROWS;   // 4096

    cvt_all<<<24576, 256>>>((const float4*)x, (const float4*)wq, (const float4*)wk,
                            (const float4*)wv, (const float4*)wo,
                            (__nv_bfloat162*)xh,  (__nv_bfloat162*)xl,
                            (__nv_bfloat162*)wqh, (__nv_bfloat162*)wql,
                            (__nv_bfloat162*)wkh, (__nv_bfloat162*)wkl,
                            (__nv_bfloat162*)wvh, (__nv_bfloat162*)wvl,
                            (__nv_bfloat162*)woh, (__nv_bfloat162*)wol);

    cudaFuncSetAttribute(gemm_mma, cudaFuncAttributeMaxDynamicSharedMemorySize, GEMM_SMEM);
    dim3 ggrid(HIDDEN / 128, M / 128);   // (16, 32)
    gemm_mma<<<ggrid, 256, GEMM_SMEM>>>(xh, xl, wqh, wql, Qp, M, HIDDEN, HIDDEN);
    gemm_mma<<<ggrid, 256, GEMM_SMEM>>>(xh, xl, wkh, wkl, Kp, M, HIDDEN, HIDDEN);
    gemm_mma<<<ggrid, 256, GEMM_SMEM>>>(xh, xl, wvh, wvl, Vp, M, HIDDEN, HIDDEN);

    cudaFuncSetAttribute(attn_kernel, cudaFuncAttributeMaxDynamicSharedMemorySize,
                         ATTN_SMEM_BYTES);
    attn_kernel<<<dim3(BATCH * NHEADS, SEQ / 64), 512, ATTN_SMEM_BYTES>>>(Qp, Kp, Vp, oh, ol);

    gemm_mma<<<ggrid, 256, GEMM_SMEM>>>(oh, ol, woh, wol, out, M, HIDDEN, HIDDEN);
}

// round 7
// speedup vs baseline: 2.2234x; 2.2234x over previous
#include <cuda_runtime.h>
#include <cuda_bf16.h>
#include <cuda_fp16.h>
#include <cstdint>

#define HIDDEN 2048
#define SEQ    2048
#define BATCH  2
#define NHEADS 16
#define HDIM   128
#define MROWS  (BATCH * SEQ)   // 4096

// ---------- scratch ----------
__device__ __nv_bfloat16 g_xh[MROWS * HIDDEN], g_xl[MROWS * HIDDEN];
__device__ __nv_bfloat16 g_oh[MROWS * HIDDEN], g_ol[MROWS * HIDDEN];
__device__ __nv_bfloat16 g_qbh[MROWS * HIDDEN], g_qbl[MROWS * HIDDEN];
__device__ __nv_bfloat16 g_kbh[MROWS * HIDDEN], g_kbl[MROWS * HIDDEN];
__device__ __half        g_vf[MROWS * HIDDEN];
__device__ __nv_bfloat16 g_wqh[HIDDEN * HIDDEN], g_wql[HIDDEN * HIDDEN];
__device__ __nv_bfloat16 g_wkh[HIDDEN * HIDDEN], g_wkl[HIDDEN * HIDDEN];
__device__ __nv_bfloat16 g_wvh[HIDDEN * HIDDEN], g_wvl[HIDDEN * HIDDEN];
__device__ __nv_bfloat16 g_woh[HIDDEN * HIDDEN], g_wol[HIDDEN * HIDDEN];

// ---------- PTX wrappers (sm_80/90-era, valid on compute_103) ----------
__device__ __forceinline__ uint32_t smem_u32(const void* p) {
    uint32_t a;
    asm("{ .reg .u64 t; cvta.to.shared.u64 t, %1; cvt.u32.u64 %0, t; }" : "=r"(a) : "l"(p));
    return a;
}
__device__ __forceinline__ void cp16(uint32_t sdst, const void* gsrc) {
    asm volatile("cp.async.cg.shared.global [%0], [%1], 16;" :: "r"(sdst), "l"(gsrc) : "memory");
}
#define CP_COMMIT() asm volatile("cp.async.commit_group;" ::: "memory")
#define CP_WAIT1()  asm volatile("cp.async.wait_group 1;" ::: "memory")

__device__ __forceinline__ void ldsm_x4(uint32_t (&r)[4], uint32_t addr) {
    asm volatile("ldmatrix.sync.aligned.m8n8.x4.shared.b16 {%0,%1,%2,%3}, [%4];"
                 : "=r"(r[0]), "=r"(r[1]), "=r"(r[2]), "=r"(r[3]) : "r"(addr));
}
__device__ __forceinline__ void ldsm_x4_t(uint32_t (&r)[4], uint32_t addr) {
    asm volatile("ldmatrix.sync.aligned.m8n8.x4.trans.shared.b16 {%0,%1,%2,%3}, [%4];"
                 : "=r"(r[0]), "=r"(r[1]), "=r"(r[2]), "=r"(r[3]) : "r"(addr));
}
__device__ __forceinline__ void mma16816(float (&d)[4], const uint32_t (&a)[4],
                                         uint32_t b0, uint32_t b1) {
    asm volatile(
        "mma.sync.aligned.m16n8k16.row.col.f32.bf16.bf16.f32 "
        "{%0,%1,%2,%3}, {%4,%5,%6,%7}, {%8,%9}, {%0,%1,%2,%3};"
        : "+f"(d[0]), "+f"(d[1]), "+f"(d[2]), "+f"(d[3])
        : "r"(a[0]), "r"(a[1]), "r"(a[2]), "r"(a[3]), "r"(b0), "r"(b1));
}
__device__ __forceinline__ void mma16816h(float (&d)[4], const uint32_t (&a)[4],
                                          uint32_t b0, uint32_t b1) {
    asm volatile(
        "mma.sync.aligned.m16n8k16.row.col.f32.f16.f16.f32 "
        "{%0,%1,%2,%3}, {%4,%5,%6,%7}, {%8,%9}, {%0,%1,%2,%3};"
        : "+f"(d[0]), "+f"(d[1]), "+f"(d[2]), "+f"(d[3])
        : "r"(a[0]), "r"(a[1]), "r"(a[2]), "r"(a[3]), "r"(b0), "r"(b1));
}
// pack (lo, hi) fp32 -> f16x2 (low half = first arg)
__device__ __forceinline__ uint32_t pack_f16x2(float lo, float hi) {
    __half2 h = __float22half2_rn(make_float2(lo, hi));
    return *(uint32_t*)&h;
}

// ---------- fused fp32 -> bf16 hi/lo split for all 5 inputs ----------
__global__ __launch_bounds__(256)
void cvt_all(const float4* __restrict__ x,  const float4* __restrict__ wq,
             const float4* __restrict__ wk, const float4* __restrict__ wv,
             const float4* __restrict__ wo,
             __nv_bfloat162* xh,  __nv_bfloat162* xl,
             __nv_bfloat162* wqh, __nv_bfloat162* wql,
             __nv_bfloat162* wkh, __nv_bfloat162* wkl,
             __nv_bfloat162* wvh, __nv_bfloat162* wvl,
             __nv_bfloat162* woh, __nv_bfloat162* wol)
{
    int bid = blockIdx.x;
    const float4* src; __nv_bfloat162 *ph, *pl; int base;
    if      (bid <  8192) { src = x;  ph = xh;  pl = xl;  base = bid; }
    else if (bid < 12288) { src = wq; ph = wqh; pl = wql; base = bid - 8192; }
    else if (bid < 16384) { src = wk; ph = wkh; pl = wkl; base = bid - 12288; }
    else if (bid < 20480) { src = wv; ph = wvh; pl = wvl; base = bid - 16384; }
    else                  { src = wo; ph = woh; pl = wol; base = bid - 20480; }
    size_t i = (size_t)base * 256 + threadIdx.x;
    float4 v = src[i];
    __nv_bfloat16 hx = __float2bfloat16(v.x);
    __nv_bfloat16 hy = __float2bfloat16(v.y);
    __nv_bfloat16 hz = __float2bfloat16(v.z);
    __nv_bfloat16 hw = __float2bfloat16(v.w);
    ph[2 * i]     = __halves2bfloat162(hx, hy);
    ph[2 * i + 1] = __halves2bfloat162(hz, hw);
    pl[2 * i]     = __halves2bfloat162(__float2bfloat16(v.x - __bfloat162float(hx)),
                                       __float2bfloat16(v.y - __bfloat162float(hy)));
    pl[2 * i + 1] = __halves2bfloat162(__float2bfloat16(v.z - __bfloat162float(hz)),
                                       __float2bfloat16(v.w - __bfloat162float(hw)));
}

// =====================================================================
// HMMA GEMM. Epilogue modes: fp32 C | bf16 hi/lo (Ch,Cl) | fp16 Cf.
// =====================================================================
#define BK       32
#define NKCH     (HIDDEN / BK)          // 64
#define ROWB     80
#define TILE_B   (128 * ROWB)           // 10240
#define STAGE_B  (4 * TILE_B)           // 40960
#define GEMM_SMEM (2 * STAGE_B)         // 81920

__global__ __launch_bounds__(256, 2)
void gemm_mma(const __nv_bfloat16* __restrict__ Ah, const __nv_bfloat16* __restrict__ Al,
              const __nv_bfloat16* __restrict__ Bh, const __nv_bfloat16* __restrict__ Bl,
              float* __restrict__ C,
              __nv_bfloat16* __restrict__ Ch, __nv_bfloat16* __restrict__ Cl,
              __half* __restrict__ Cf,
              int M, int N, int K)
{
    extern __shared__ __align__(128) char smem[];
    const uint32_t sbase = smem_u32(smem);
    const int tid  = threadIdx.x;
    const int wid  = tid >> 5;
    const int lane = tid & 31;
    const int wm   = wid & 3;
    const int wn   = wid >> 2;
    const size_t brow = (size_t)blockIdx.y * 128;
    const size_t bcol = (size_t)blockIdx.x * 128;

    const int row  = tid >> 1;
    const int segq = (tid & 1) * 2;
    const uint32_t soff0 = (uint32_t)(row * ROWB + segq * 16);
    const uint32_t soff1 = soff0 + 16;

    const size_t Kb = (size_t)K * 2;
    const char* pAh = (const char*)Ah + (brow + row) * Kb + segq * 16;
    const char* pAl = (const char*)Al + (brow + row) * Kb + segq * 16;
    const char* pBh = (const char*)Bh + (bcol + row) * Kb + segq * 16;
    const char* pBl = (const char*)Bl + (bcol + row) * Kb + segq * 16;

#define LOAD_CHUNK(c, s) do {                                    \
        uint32_t sb_ = sbase + (uint32_t)(s) * STAGE_B;          \
        size_t g_ = (size_t)(c) * 64;                            \
        cp16(sb_ + 0 * TILE_B + soff0, pAh + g_);                \
        cp16(sb_ + 0 * TILE_B + soff1, pAh + g_ + 16);           \
        cp16(sb_ + 1 * TILE_B + soff0, pAl + g_);                \
        cp16(sb_ + 1 * TILE_B + soff1, pAl + g_ + 16);           \
        cp16(sb_ + 2 * TILE_B + soff0, pBh + g_);                \
        cp16(sb_ + 2 * TILE_B + soff1, pBh + g_ + 16);           \
        cp16(sb_ + 3 * TILE_B + soff0, pBl + g_);                \
        cp16(sb_ + 3 * TILE_B + soff1, pBl + g_ + 16);           \
    } while (0)

    const int rA   = wm * 32 + (lane & 15);
    const int aSeg = lane >> 4;
    const int rB   = wn * 64 + ((lane >> 4) << 3) + (lane & 7);
    const int bSeg = (lane >> 3) & 1;

    float acc[2][8][4];
#pragma unroll
    for (int mt = 0; mt < 2; ++mt)
#pragma unroll
        for (int nt = 0; nt < 8; ++nt)
#pragma unroll
            for (int q = 0; q < 4; ++q) acc[mt][nt][q] = 0.f;

    LOAD_CHUNK(0, 0); CP_COMMIT();
    LOAD_CHUNK(1, 1); CP_COMMIT();

    for (int c = 0; c < NKCH; ++c) {
        CP_WAIT1();
        __syncthreads();

        const uint32_t sb = sbase + (uint32_t)(c & 1) * STAGE_B;

#pragma unroll
        for (int k16 = 0; k16 < 2; ++k16) {
            uint32_t ah[2][4], al[2][4];
#pragma unroll
            for (int mt = 0; mt < 2; ++mt) {
                uint32_t byteoff = (uint32_t)((rA + mt * 16) * ROWB + (2 * k16 + aSeg) * 16);
                ldsm_x4(ah[mt], sb + 0 * TILE_B + byteoff);
                ldsm_x4(al[mt], sb + 1 * TILE_B + byteoff);
            }
            uint32_t bh[4][4];
#pragma unroll
            for (int np = 0; np < 4; ++np) {
                uint32_t byteoff = (uint32_t)((rB + np * 16) * ROWB + (2 * k16 + bSeg) * 16);
                ldsm_x4(bh[np], sb + 2 * TILE_B + byteoff);
            }
#pragma unroll
            for (int np = 0; np < 4; ++np)
#pragma unroll
                for (int mt = 0; mt < 2; ++mt) {
                    mma16816(acc[mt][2 * np + 0], ah[mt], bh[np][0], bh[np][1]);
                    mma16816(acc[mt][2 * np + 1], ah[mt], bh[np][2], bh[np][3]);
                }
#pragma unroll
            for (int np = 0; np < 4; ++np)
#pragma unroll
                for (int mt = 0; mt < 2; ++mt) {
                    mma16816(acc[mt][2 * np + 0], al[mt], bh[np][0], bh[np][1]);
                    mma16816(acc[mt][2 * np + 1], al[mt], bh[np][2], bh[np][3]);
                }
#pragma unroll
            for (int np = 0; np < 4; ++np) {
                uint32_t byteoff = (uint32_t)((rB + np * 16) * ROWB + (2 * k16 + bSeg) * 16);
                uint32_t bl[4];
                ldsm_x4(bl, sb + 3 * TILE_B + byteoff);
#pragma unroll
                for (int mt = 0; mt < 2; ++mt) {
                    mma16816(acc[mt][2 * np + 0], ah[mt], bl[0], bl[1]);
                    mma16816(acc[mt][2 * np + 1], ah[mt], bl[2], bl[3]);
                }
            }
        }

        __syncthreads();
        if (c + 2 < NKCH) LOAD_CHUNK(c + 2, c & 1);
        CP_COMMIT();
    }

#pragma unroll
    for (int mt = 0; mt < 2; ++mt) {
        size_t r0 = brow + wm * 32 + mt * 16 + (lane >> 2);
#pragma unroll
        for (int nt = 0; nt < 8; ++nt) {
            size_t col = bcol + wn * 64 + nt * 8 + 2 * (lane & 3);
            if (C) {
                *(float2*)&C[r0 * (size_t)N + col]       = make_float2(acc[mt][nt][0], acc[mt][nt][1]);
                *(float2*)&C[(r0 + 8) * (size_t)N + col] = make_float2(acc[mt][nt][2], acc[mt][nt][3]);
            } else if (Cf) {
#pragma unroll
                for (int half_ = 0; half_ < 2; ++half_) {
                    size_t idx = (r0 + 8 * half_) * (size_t)N + col;
                    *(__half2*)&Cf[idx] = __float22half2_rn(
                        make_float2(acc[mt][nt][2 * half_], acc[mt][nt][2 * half_ + 1]));
                }
            } else {
#pragma unroll
                for (int half_ = 0; half_ < 2; ++half_) {
                    float v0 = acc[mt][nt][2 * half_ + 0];
                    float v1 = acc[mt][nt][2 * half_ + 1];
                    __nv_bfloat16 h0 = __float2bfloat16(v0);
                    __nv_bfloat16 h1 = __float2bfloat16(v1);
                    size_t idx = (r0 + 8 * half_) * (size_t)N + col;
                    *(__nv_bfloat162*)&Ch[idx] = __halves2bfloat162(h0, h1);
                    *(__nv_bfloat162*)&Cl[idx] = __halves2bfloat162(
                        __float2bfloat16(v0 - __bfloat162float(h0)),
                        __float2bfloat16(v1 - __bfloat162float(h1)));
                }
            }
        }
    }
}

// =====================================================================
// FlashAttention-2 on HMMA.
// Scores: 3-pass hi/lo bf16 (fp32 accum). PV: fp16 P and fp16 V, 1 pass.
// smem: Qh @0 | Ql @34816 | stage s @69632+s*52224: Kh | Kl(+17408) | V(+34816)
// =====================================================================
#define QT        128
#define SROW      272
#define AQL_OFF   34816
#define AST_OFF   69632
#define AST_SZ    52224
#define AKL_OFF   17408
#define AV_OFF    34816
#define ATTN_SMEM 174080
#define NKT       (SEQ / 64)   // 32

__global__ __launch_bounds__(256, 1)
void attn_mma(const __nv_bfloat16* __restrict__ Qh, const __nv_bfloat16* __restrict__ Ql,
              const __nv_bfloat16* __restrict__ Kh, const __nv_bfloat16* __restrict__ Kl,
              const __half* __restrict__ Vf,
              __nv_bfloat16* __restrict__ Oh, __nv_bfloat16* __restrict__ Ol)
{
    extern __shared__ __align__(128) char smem[];
    const uint32_t sb = smem_u32(smem);
    const int tid  = threadIdx.x;
    const int wid  = tid >> 5;
    const int lane = tid & 31;
    const int b    = blockIdx.x >> 4;
    const int h    = blockIdx.x & 15;
    const int qt   = blockIdx.y;

    const float scale = 0.08838834764831843f;   // 1/sqrt(128)
    const size_t hoff  = (size_t)h * HDIM;
    const size_t qrow0 = (size_t)b * SEQ + (size_t)qt * QT;
    const size_t krow0 = (size_t)b * SEQ;

#pragma unroll
    for (int it = 0; it < 8; ++it) {
        int idx = it * 256 + tid;
        int r   = idx >> 4;
        int ch  = idx & 15;
        size_t g = ((qrow0 + r) * HIDDEN + hoff + ch * 8) * 2;
        uint32_t d = sb + (uint32_t)(r * SROW + ch * 16);
        cp16(d,           (const char*)Qh + g);
        cp16(d + AQL_OFF, (const char*)Ql + g);
    }
#define LOAD_KV(c, s) do {                                                     \
        uint32_t st_ = sb + AST_OFF + (uint32_t)(s) * AST_SZ;                  \
        _Pragma("unroll")                                                      \
        for (int it_ = 0; it_ < 4; ++it_) {                                    \
            int idx_ = it_ * 256 + tid;                                        \
            int r_  = idx_ >> 4;                                               \
            int ch_ = idx_ & 15;                                               \
            size_t g_ = ((krow0 + (size_t)(c) * 64 + r_) * HIDDEN + hoff + ch_ * 8) * 2; \
            uint32_t d_ = st_ + (uint32_t)(r_ * SROW + ch_ * 16);              \
            cp16(d_,           (const char*)Kh + g_);                          \
            cp16(d_ + AKL_OFF, (const char*)Kl + g_);                          \
            cp16(d_ + AV_OFF,  (const char*)Vf + g_);                          \
        }                                                                      \
    } while (0)

    LOAD_KV(0, 0); CP_COMMIT();
    LOAD_KV(1, 1); CP_COMMIT();
    CP_WAIT1();
    __syncthreads();

    const int arow = lane & 15;
    const int aseg = lane >> 4;
    const uint32_t qbase = sb + (uint32_t)((wid * 16 + arow) * SROW + aseg * 16);
    uint32_t qh[8][4];
#pragma unroll
    for (int ks = 0; ks < 8; ++ks) ldsm_x4(qh[ks], qbase + ks * 32);
    const uint32_t qlbase = qbase + AQL_OFF;

    float Oacc[16][4];
#pragma unroll
    for (int nt = 0; nt < 16; ++nt)
#pragma unroll
        for (int q = 0; q < 4; ++q) Oacc[nt][q] = 0.f;
    float m0 = -1e30f, m1 = -1e30f, l0 = 0.f, l1 = 0.f;

    const int brow = ((lane >> 4) << 3) + (lane & 7);
    const int bseg = (lane >> 3) & 1;

    for (int kt = 0; kt < NKT; ++kt) {
        const uint32_t st = sb + AST_OFF + (uint32_t)(kt & 1) * AST_SZ;

        float S[8][4];
#pragma unroll
        for (int nt = 0; nt < 8; ++nt)
#pragma unroll
            for (int q = 0; q < 4; ++q) S[nt][q] = 0.f;

#pragma unroll
        for (int ks = 0; ks < 8; ++ks) {
            uint32_t koff = (uint32_t)(brow * SROW + ks * 32 + bseg * 16);
            uint32_t kh4[4][4];
#pragma unroll
            for (int p = 0; p < 4; ++p) ldsm_x4(kh4[p], st + p * (16 * SROW) + koff);
#pragma unroll
            for (int p = 0; p < 4; ++p) {
                mma16816(S[2 * p + 0], qh[ks], kh4[p][0], kh4[p][1]);
                mma16816(S[2 * p + 1], qh[ks], kh4[p][2], kh4[p][3]);
            }
            uint32_t ql4[4];
            ldsm_x4(ql4, qlbase + ks * 32);
#pragma unroll
            for (int p = 0; p < 4; ++p) {
                mma16816(S[2 * p + 0], ql4, kh4[p][0], kh4[p][1]);
                mma16816(S[2 * p + 1], ql4, kh4[p][2], kh4[p][3]);
            }
#pragma unroll
            for (int p = 0; p < 4; ++p) {
                uint32_t kl4[4];
                ldsm_x4(kl4, st + AKL_OFF + p * (16 * SROW) + koff);
                mma16816(S[2 * p + 0], qh[ks], kl4[0], kl4[1]);
                mma16816(S[2 * p + 1], qh[ks], kl4[2], kl4[3]);
            }
        }

        // ---- online softmax ----
        float mx0 = -1e30f, mx1 = -1e30f;
#pragma unroll
        for (int nt = 0; nt < 8; ++nt) {
            mx0 = fmaxf(mx0, fmaxf(S[nt][0], S[nt][1]));
            mx1 = fmaxf(mx1, fmaxf(S[nt][2], S[nt][3]));
        }
        mx0 = fmaxf(mx0, __shfl_xor_sync(0xffffffffu, mx0, 1));
        mx0 = fmaxf(mx0, __shfl_xor_sync(0xffffffffu, mx0, 2));
        mx1 = fmaxf(mx1, __shfl_xor_sync(0xffffffffu, mx1, 1));
        mx1 = fmaxf(mx1, __shfl_xor_sync(0xffffffffu, mx1, 2));
        float mn0 = fmaxf(m0, mx0), mn1 = fmaxf(m1, mx1);
        float cf0 = __expf(scale * (m0 - mn0));
        float cf1 = __expf(scale * (m1 - mn1));
        m0 = mn0; m1 = mn1;
        float bb0 = -scale * mn0, bb1 = -scale * mn1;
        float rs0 = 0.f, rs1 = 0.f;
#pragma unroll
        for (int nt = 0; nt < 8; ++nt) {
            S[nt][0] = __expf(fmaf(S[nt][0], scale, bb0));
            S[nt][1] = __expf(fmaf(S[nt][1], scale, bb0));
            S[nt][2] = __expf(fmaf(S[nt][2], scale, bb1));
            S[nt][3] = __expf(fmaf(S[nt][3], scale, bb1));
            rs0 += S[nt][0] + S[nt][1];
            rs1 += S[nt][2] + S[nt][3];
        }
        rs0 += __shfl_xor_sync(0xffffffffu, rs0, 1);
        rs0 += __shfl_xor_sync(0xffffffffu, rs0, 2);
        rs1 += __shfl_xor_sync(0xffffffffu, rs1, 1);
        rs1 += __shfl_xor_sync(0xffffffffu, rs1, 2);
        l0 = l0 * cf0 + rs0;
        l1 = l1 * cf1 + rs1;

#pragma unroll
        for (int nt = 0; nt < 16; ++nt) {
            Oacc[nt][0] *= cf0; Oacc[nt][1] *= cf0;
            Oacc[nt][2] *= cf1; Oacc[nt][3] *= cf1;
        }
        // pack P to fp16 A-frags
        uint32_t pa[4][4];
#pragma unroll
        for (int t = 0; t < 4; ++t) {
            pa[t][0] = pack_f16x2(S[2 * t][0],     S[2 * t][1]);
            pa[t][1] = pack_f16x2(S[2 * t][2],     S[2 * t][3]);
            pa[t][2] = pack_f16x2(S[2 * t + 1][0], S[2 * t + 1][1]);
            pa[t][3] = pack_f16x2(S[2 * t + 1][2], S[2 * t + 1][3]);
        }

        // ---- PV (fp16 x fp16 -> fp32) ----
        const uint32_t vbase = st + AV_OFF;
#pragma unroll
        for (int t = 0; t < 4; ++t) {
            uint32_t rowoff = vbase + (uint32_t)((t * 16 + (lane & 15)) * SROW + (lane >> 4) * 16);
#pragma unroll
            for (int dp = 0; dp < 8; ++dp) {
                uint32_t vb[4];
                ldsm_x4_t(vb, rowoff + dp * 32);
                mma16816h(Oacc[2 * dp + 0], pa[t], vb[0], vb[1]);
                mma16816h(Oacc[2 * dp + 1], pa[t], vb[2], vb[3]);
            }
        }

        __syncthreads();
        if (kt + 2 < NKT) LOAD_KV(kt + 2, kt & 1);
        CP_COMMIT();
        if (kt + 1 < NKT) { CP_WAIT1(); __syncthreads(); }
    }

    // ---- epilogue ----
    float inv0 = 1.0f / l0, inv1 = 1.0f / l1;
    int r = wid * 16 + (lane >> 2);
    size_t g0 = (qrow0 + r) * HIDDEN + hoff;
    size_t g1 = g0 + 8 * HIDDEN;
#pragma unroll
    for (int nt = 0; nt < 16; ++nt) {
        int col = nt * 8 + 2 * (lane & 3);
        float v0 = Oacc[nt][0] * inv0, v1 = Oacc[nt][1] * inv0;
        float v2 = Oacc[nt][2] * inv1, v3 = Oacc[nt][3] * inv1;
        __nv_bfloat16 h0 = __float2bfloat16(v0), h1 = __float2bfloat16(v1);
        __nv_bfloat16 h2 = __float2bfloat16(v2), h3 = __float2bfloat16(v3);
        *(__nv_bfloat162*)&Oh[g0 + col] = __halves2bfloat162(h0, h1);
        *(__nv_bfloat162*)&Oh[g1 + col] = __halves2bfloat162(h2, h3);
        *(__nv_bfloat162*)&Ol[g0 + col] = __halves2bfloat162(
            __float2bfloat16(v0 - __bfloat162float(h0)),
            __float2bfloat16(v1 - __bfloat162float(h1)));
        *(__nv_bfloat162*)&Ol[g1 + col] = __halves2bfloat162(
            __float2bfloat16(v2 - __bfloat162float(h2)),
            __float2bfloat16(v3 - __bfloat162float(h3)));
    }
}

// =====================================================================
extern "C" void kernel_launch(void* const* d_in, const int* in_sizes, int n_in,
                              void* d_out, int out_size)
{
    const float* x  = (const float*)d_in[0];
    const float* wq = (const float*)d_in[1];
    const float* wk = (const float*)d_in[2];
    const float* wv = (const float*)d_in[3];
    const float* wo = (const float*)d_in[4];
    float* out = (float*)d_out;

    __nv_bfloat16 *xh, *xl, *oh, *ol;
    __nv_bfloat16 *qbh, *qbl, *kbh, *kbl;
    __half *vf;
    __nv_bfloat16 *wqh, *wql, *wkh, *wkl, *wvh, *wvl, *woh, *wol;
    cudaGetSymbolAddress((void**)&xh, g_xh);   cudaGetSymbolAddress((void**)&xl, g_xl);
    cudaGetSymbolAddress((void**)&oh, g_oh);   cudaGetSymbolAddress((void**)&ol, g_ol);
    cudaGetSymbolAddress((void**)&qbh, g_qbh); cudaGetSymbolAddress((void**)&qbl, g_qbl);
    cudaGetSymbolAddress((void**)&kbh, g_kbh); cudaGetSymbolAddress((void**)&kbl, g_kbl);
    cudaGetSymbolAddress((void**)&vf, g_vf);
    cudaGetSymbolAddress((void**)&wqh, g_wqh); cudaGetSymbolAddress((void**)&wql, g_wql);
    cudaGetSymbolAddress((void**)&wkh, g_wkh); cudaGetSymbolAddress((void**)&wkl, g_wkl);
    cudaGetSymbolAddress((void**)&wvh, g_wvh); cudaGetSymbolAddress((void**)&wvl, g_wvl);
    cudaGetSymbolAddress((void**)&woh, g_woh); cudaGetSymbolAddress((void**)&wol, g_wol);

    const int M = MROWS;   // 4096

    cvt_all<<<24576, 256>>>((const float4*)x, (const float4*)wq, (const float4*)wk,
                            (const float4*)wv, (const float4*)wo,
                            (__nv_bfloat162*)xh,  (__nv_bfloat162*)xl,
                            (__nv_bfloat162*)wqh, (__nv_bfloat162*)wql,
                            (__nv_bfloat162*)wkh, (__nv_bfloat162*)wkl,
                            (__nv_bfloat162*)wvh, (__nv_bfloat162*)wvl,
                            (__nv_bfloat162*)woh, (__nv_bfloat162*)wol);

    cudaFuncSetAttribute(gemm_mma, cudaFuncAttributeMaxDynamicSharedMemorySize, GEMM_SMEM);
    dim3 ggrid(HIDDEN / 128, M / 128);   // (16, 32)
    gemm_mma<<<ggrid, 256, GEMM_SMEM>>>(xh, xl, wqh, wql, nullptr, qbh, qbl, nullptr, M, HIDDEN, HIDDEN);
    gemm_mma<<<ggrid, 256, GEMM_SMEM>>>(xh, xl, wkh, wkl, nullptr, kbh, kbl, nullptr, M, HIDDEN, HIDDEN);
    gemm_mma<<<ggrid, 256, GEMM_SMEM>>>(xh, xl, wvh, wvl, nullptr, nullptr, nullptr, vf, M, HIDDEN, HIDDEN);

    cudaFuncSetAttribute(attn_mma, cudaFuncAttributeMaxDynamicSharedMemorySize, ATTN_SMEM);
    attn_mma<<<dim3(BATCH * NHEADS, SEQ / QT), 256, ATTN_SMEM>>>(qbh, qbl, kbh, kbl, vf, oh, ol);

    gemm_mma<<<ggrid, 256, GEMM_SMEM>>>(oh, ol, woh, wol, out, nullptr, nullptr, nullptr, M, HIDDEN, HIDDEN);
}

// round 8
// speedup vs baseline: 2.4416x; 1.0982x over previous
#include <cuda_runtime.h>
#include <cuda_bf16.h>
#include <cuda_fp16.h>
#include <cstdint>

#define HIDDEN 2048
#define SEQ    2048
#define BATCH  2
#define NHEADS 16
#define HDIM   128
#define MROWS  (BATCH * SEQ)   // 4096

// ---------- scratch ----------
__device__ __nv_bfloat16 g_xh[MROWS * HIDDEN], g_xl[MROWS * HIDDEN];
__device__ __nv_bfloat16 g_oh[MROWS * HIDDEN], g_ol[MROWS * HIDDEN];
__device__ __nv_bfloat16 g_qbh[MROWS * HIDDEN], g_qbl[MROWS * HIDDEN];
__device__ __nv_bfloat16 g_kbh[MROWS * HIDDEN], g_kbl[MROWS * HIDDEN];
__device__ __half        g_vf[MROWS * HIDDEN];
__device__ __nv_bfloat16 g_wqh[HIDDEN * HIDDEN], g_wql[HIDDEN * HIDDEN];
__device__ __nv_bfloat16 g_wkh[HIDDEN * HIDDEN], g_wkl[HIDDEN * HIDDEN];
__device__ __nv_bfloat16 g_wvh[HIDDEN * HIDDEN], g_wvl[HIDDEN * HIDDEN];
__device__ __nv_bfloat16 g_woh[HIDDEN * HIDDEN], g_wol[HIDDEN * HIDDEN];

// ---------- PTX wrappers (sm_80/90-era, valid on compute_103) ----------
__device__ __forceinline__ uint32_t smem_u32(const void* p) {
    uint32_t a;
    asm("{ .reg .u64 t; cvta.to.shared.u64 t, %1; cvt.u32.u64 %0, t; }" : "=r"(a) : "l"(p));
    return a;
}
__device__ __forceinline__ void cp16(uint32_t sdst, const void* gsrc) {
    asm volatile("cp.async.cg.shared.global [%0], [%1], 16;" :: "r"(sdst), "l"(gsrc) : "memory");
}
#define CP_COMMIT() asm volatile("cp.async.commit_group;" ::: "memory")
#define CP_WAIT1()  asm volatile("cp.async.wait_group 1;" ::: "memory")
#define CP_WAIT2()  asm volatile("cp.async.wait_group 2;" ::: "memory")

__device__ __forceinline__ void ldsm_x4(uint32_t (&r)[4], uint32_t addr) {
    asm volatile("ldmatrix.sync.aligned.m8n8.x4.shared.b16 {%0,%1,%2,%3}, [%4];"
                 : "=r"(r[0]), "=r"(r[1]), "=r"(r[2]), "=r"(r[3]) : "r"(addr));
}
__device__ __forceinline__ void ldsm_x4_t(uint32_t (&r)[4], uint32_t addr) {
    asm volatile("ldmatrix.sync.aligned.m8n8.x4.trans.shared.b16 {%0,%1,%2,%3}, [%4];"
                 : "=r"(r[0]), "=r"(r[1]), "=r"(r[2]), "=r"(r[3]) : "r"(addr));
}
__device__ __forceinline__ void mma16816(float (&d)[4], const uint32_t (&a)[4],
                                         uint32_t b0, uint32_t b1) {
    asm volatile(
        "mma.sync.aligned.m16n8k16.row.col.f32.bf16.bf16.f32 "
        "{%0,%1,%2,%3}, {%4,%5,%6,%7}, {%8,%9}, {%0,%1,%2,%3};"
        : "+f"(d[0]), "+f"(d[1]), "+f"(d[2]), "+f"(d[3])
        : "r"(a[0]), "r"(a[1]), "r"(a[2]), "r"(a[3]), "r"(b0), "r"(b1));
}
__device__ __forceinline__ void mma16816h(float (&d)[4], const uint32_t (&a)[4],
                                          uint32_t b0, uint32_t b1) {
    asm volatile(
        "mma.sync.aligned.m16n8k16.row.col.f32.f16.f16.f32 "
        "{%0,%1,%2,%3}, {%4,%5,%6,%7}, {%8,%9}, {%0,%1,%2,%3};"
        : "+f"(d[0]), "+f"(d[1]), "+f"(d[2]), "+f"(d[3])
        : "r"(a[0]), "r"(a[1]), "r"(a[2]), "r"(a[3]), "r"(b0), "r"(b1));
}
__device__ __forceinline__ uint32_t pack_f16x2(float lo, float hi) {
    __half2 h = __float22half2_rn(make_float2(lo, hi));
    return *(uint32_t*)&h;
}

// ---------- fused fp32 -> bf16 hi/lo split for all 5 inputs ----------
__global__ __launch_bounds__(256)
void cvt_all(const float4* __restrict__ x,  const float4* __restrict__ wq,
             const float4* __restrict__ wk, const float4* __restrict__ wv,
             const float4* __restrict__ wo,
             __nv_bfloat162* xh,  __nv_bfloat162* xl,
             __nv_bfloat162* wqh, __nv_bfloat162* wql,
             __nv_bfloat162* wkh, __nv_bfloat162* wkl,
             __nv_bfloat162* wvh, __nv_bfloat162* wvl,
             __nv_bfloat162* woh, __nv_bfloat162* wol)
{
    int bid = blockIdx.x;
    const float4* src; __nv_bfloat162 *ph, *pl; int base;
    if      (bid <  8192) { src = x;  ph = xh;  pl = xl;  base = bid; }
    else if (bid < 12288) { src = wq; ph = wqh; pl = wql; base = bid - 8192; }
    else if (bid < 16384) { src = wk; ph = wkh; pl = wkl; base = bid - 12288; }
    else if (bid < 20480) { src = wv; ph = wvh; pl = wvl; base = bid - 16384; }
    else                  { src = wo; ph = woh; pl = wol; base = bid - 20480; }
    size_t i = (size_t)base * 256 + threadIdx.x;
    float4 v = src[i];
    __nv_bfloat16 hx = __float2bfloat16(v.x);
    __nv_bfloat16 hy = __float2bfloat16(v.y);
    __nv_bfloat16 hz = __float2bfloat16(v.z);
    __nv_bfloat16 hw = __float2bfloat16(v.w);
    ph[2 * i]     = __halves2bfloat162(hx, hy);
    ph[2 * i + 1] = __halves2bfloat162(hz, hw);
    pl[2 * i]     = __halves2bfloat162(__float2bfloat16(v.x - __bfloat162float(hx)),
                                       __float2bfloat16(v.y - __bfloat162float(hy)));
    pl[2 * i + 1] = __halves2bfloat162(__float2bfloat16(v.z - __bfloat162float(hz)),
                                       __float2bfloat16(v.w - __bfloat162float(hw)));
}

// =====================================================================
// HMMA GEMM. 128x128 CTA tile, 8 warps (4m x 2n), BK=32.
// 64B smem rows + XOR swizzle (seg ^ (row>>1)&3) -> conflict-free ldsm.
// 3-stage pipeline, ONE sync per chunk, loads issued before wait.
// =====================================================================
#define BK       32
#define NKCH     (HIDDEN / BK)          // 64
#define ROWB     64
#define TILE_B   (128 * ROWB)           // 8192
#define STAGE_B  (4 * TILE_B)           // 32768
#define GEMM_SMEM (3 * STAGE_B)         // 98304

__global__ __launch_bounds__(256, 2)
void gemm_mma(const __nv_bfloat16* __restrict__ Ah, const __nv_bfloat16* __restrict__ Al,
              const __nv_bfloat16* __restrict__ Bh, const __nv_bfloat16* __restrict__ Bl,
              float* __restrict__ C,
              __nv_bfloat16* __restrict__ Ch, __nv_bfloat16* __restrict__ Cl,
              __half* __restrict__ Cf,
              int M, int N, int K)
{
    extern __shared__ __align__(128) char smem[];
    const uint32_t sbase = smem_u32(smem);
    const int tid  = threadIdx.x;
    const int wid  = tid >> 5;
    const int lane = tid & 31;
    const int wm   = wid & 3;
    const int wn   = wid >> 2;
    const size_t brow = (size_t)blockIdx.y * 128;
    const size_t bcol = (size_t)blockIdx.x * 128;

    // cp.async slots: row = tid>>1, segs sp, sp+1 (swizzled)
    const int row = tid >> 1;
    const int sp  = (tid & 1) * 2;
    const int wmsk = (row >> 1) & 3;
    const uint32_t soff0 = (uint32_t)(row * ROWB + ((sp    ) ^ wmsk) * 16);
    const uint32_t soff1 = (uint32_t)(row * ROWB + ((sp + 1) ^ wmsk) * 16);

    const size_t Kb = (size_t)K * 2;
    const char* pAh = (const char*)Ah + (brow + row) * Kb + sp * 16;
    const char* pAl = (const char*)Al + (brow + row) * Kb + sp * 16;
    const char* pBh = (const char*)Bh + (bcol + row) * Kb + sp * 16;
    const char* pBl = (const char*)Bl + (bcol + row) * Kb + sp * 16;

#define LOAD_CHUNK(c, s) do {                                    \
        uint32_t sb_ = sbase + (uint32_t)(s) * STAGE_B;          \
        size_t g_ = (size_t)(c) * 64;                            \
        cp16(sb_ + 0 * TILE_B + soff0, pAh + g_);                \
        cp16(sb_ + 0 * TILE_B + soff1, pAh + g_ + 16);           \
        cp16(sb_ + 1 * TILE_B + soff0, pAl + g_);                \
        cp16(sb_ + 1 * TILE_B + soff1, pAl + g_ + 16);           \
        cp16(sb_ + 2 * TILE_B + soff0, pBh + g_);                \
        cp16(sb_ + 2 * TILE_B + soff1, pBh + g_ + 16);           \
        cp16(sb_ + 3 * TILE_B + soff0, pBl + g_);                \
        cp16(sb_ + 3 * TILE_B + soff1, pBl + g_ + 16);           \
    } while (0)

    // ldsm addressing (swizzled); (r>>1)&3 invariant under +16 row offsets
    const int rA    = wm * 32 + (lane & 15);
    const int aSeg  = lane >> 4;
    const int maskA = (rA >> 1) & 3;
    const int rB    = wn * 64 + ((lane >> 4) << 3) + (lane & 7);
    const int bSeg  = (lane >> 3) & 1;
    const int maskB = (rB >> 1) & 3;

    float acc[2][8][4];
#pragma unroll
    for (int mt = 0; mt < 2; ++mt)
#pragma unroll
        for (int nt = 0; nt < 8; ++nt)
#pragma unroll
            for (int q = 0; q < 4; ++q) acc[mt][nt][q] = 0.f;

    LOAD_CHUNK(0, 0); CP_COMMIT();
    LOAD_CHUNK(1, 1); CP_COMMIT();

    int stage = 0;
    for (int c = 0; c < NKCH; ++c) {
        __syncthreads();                        // all warps done with chunk c-1
        if (c + 2 < NKCH) {
            int s2 = stage + 2; if (s2 >= 3) s2 -= 3;
            LOAD_CHUNK(c + 2, s2);              // overwrites chunk c-1's stage
        }
        CP_COMMIT();
        CP_WAIT2();                             // chunk c's data complete

        const uint32_t sb = sbase + (uint32_t)stage * STAGE_B;

#pragma unroll
        for (int k16 = 0; k16 < 2; ++k16) {
            uint32_t ah[2][4], al[2][4];
#pragma unroll
            for (int mt = 0; mt < 2; ++mt) {
                uint32_t byteoff = (uint32_t)((rA + mt * 16) * ROWB +
                                              ((2 * k16 + aSeg) ^ maskA) * 16);
                ldsm_x4(ah[mt], sb + 0 * TILE_B + byteoff);
                ldsm_x4(al[mt], sb + 1 * TILE_B + byteoff);
            }
            uint32_t bh[4][4];
#pragma unroll
            for (int np = 0; np < 4; ++np) {
                uint32_t byteoff = (uint32_t)((rB + np * 16) * ROWB +
                                              ((2 * k16 + bSeg) ^ maskB) * 16);
                ldsm_x4(bh[np], sb + 2 * TILE_B + byteoff);
            }
#pragma unroll
            for (int np = 0; np < 4; ++np)
#pragma unroll
                for (int mt = 0; mt < 2; ++mt) {
                    mma16816(acc[mt][2 * np + 0], ah[mt], bh[np][0], bh[np][1]);
                    mma16816(acc[mt][2 * np + 1], ah[mt], bh[np][2], bh[np][3]);
                }
#pragma unroll
            for (int np = 0; np < 4; ++np)
#pragma unroll
                for (int mt = 0; mt < 2; ++mt) {
                    mma16816(acc[mt][2 * np + 0], al[mt], bh[np][0], bh[np][1]);
                    mma16816(acc[mt][2 * np + 1], al[mt], bh[np][2], bh[np][3]);
                }
#pragma unroll
            for (int np = 0; np < 4; ++np) {
                uint32_t byteoff = (uint32_t)((rB + np * 16) * ROWB +
                                              ((2 * k16 + bSeg) ^ maskB) * 16);
                uint32_t bl[4];
                ldsm_x4(bl, sb + 3 * TILE_B + byteoff);
#pragma unroll
                for (int mt = 0; mt < 2; ++mt) {
                    mma16816(acc[mt][2 * np + 0], ah[mt], bl[0], bl[1]);
                    mma16816(acc[mt][2 * np + 1], ah[mt], bl[2], bl[3]);
                }
            }
        }
        stage = (stage == 2) ? 0 : stage + 1;
    }

#pragma unroll
    for (int mt = 0; mt < 2; ++mt) {
        size_t r0 = brow + wm * 32 + mt * 16 + (lane >> 2);
#pragma unroll
        for (int nt = 0; nt < 8; ++nt) {
            size_t col = bcol + wn * 64 + nt * 8 + 2 * (lane & 3);
            if (C) {
                *(float2*)&C[r0 * (size_t)N + col]       = make_float2(acc[mt][nt][0], acc[mt][nt][1]);
                *(float2*)&C[(r0 + 8) * (size_t)N + col] = make_float2(acc[mt][nt][2], acc[mt][nt][3]);
            } else if (Cf) {
#pragma unroll
                for (int half_ = 0; half_ < 2; ++half_) {
                    size_t idx = (r0 + 8 * half_) * (size_t)N + col;
                    *(__half2*)&Cf[idx] = __float22half2_rn(
                        make_float2(acc[mt][nt][2 * half_], acc[mt][nt][2 * half_ + 1]));
                }
            } else {
#pragma unroll
                for (int half_ = 0; half_ < 2; ++half_) {
                    float v0 = acc[mt][nt][2 * half_ + 0];
                    float v1 = acc[mt][nt][2 * half_ + 1];
                    __nv_bfloat16 h0 = __float2bfloat16(v0);
                    __nv_bfloat16 h1 = __float2bfloat16(v1);
                    size_t idx = (r0 + 8 * half_) * (size_t)N + col;
                    *(__nv_bfloat162*)&Ch[idx] = __halves2bfloat162(h0, h1);
                    *(__nv_bfloat162*)&Cl[idx] = __halves2bfloat162(
                        __float2bfloat16(v0 - __bfloat162float(h0)),
                        __float2bfloat16(v1 - __bfloat162float(h1)));
                }
            }
        }
    }
}

// =====================================================================
// FlashAttention-2 on HMMA. 3-stage KV pipeline, ONE sync per tile.
// smem: Qh @0 | Ql @34816 | stage s @69632+s*52224: Kh | Kl(+17408) | V(+34816)
// total 226304 bytes.
// =====================================================================
#define QT        128
#define SROW      272
#define AQL_OFF   34816
#define AST_OFF   69632
#define AST_SZ    52224
#define AKL_OFF   17408
#define AV_OFF    34816
#define ATTN_SMEM 226304
#define NKT       (SEQ / 64)   // 32

__global__ __launch_bounds__(256, 1)
void attn_mma(const __nv_bfloat16* __restrict__ Qh, const __nv_bfloat16* __restrict__ Ql,
              const __nv_bfloat16* __restrict__ Kh, const __nv_bfloat16* __restrict__ Kl,
              const __half* __restrict__ Vf,
              __nv_bfloat16* __restrict__ Oh, __nv_bfloat16* __restrict__ Ol)
{
    extern __shared__ __align__(128) char smem[];
    const uint32_t sb = smem_u32(smem);
    const int tid  = threadIdx.x;
    const int wid  = tid >> 5;
    const int lane = tid & 31;
    const int b    = blockIdx.x >> 4;
    const int h    = blockIdx.x & 15;
    const int qt   = blockIdx.y;

    const float scale = 0.08838834764831843f;   // 1/sqrt(128)
    const size_t hoff  = (size_t)h * HDIM;
    const size_t qrow0 = (size_t)b * SEQ + (size_t)qt * QT;
    const size_t krow0 = (size_t)b * SEQ;

#pragma unroll
    for (int it = 0; it < 8; ++it) {
        int idx = it * 256 + tid;
        int r   = idx >> 4;
        int ch  = idx & 15;
        size_t g = ((qrow0 + r) * HIDDEN + hoff + ch * 8) * 2;
        uint32_t d = sb + (uint32_t)(r * SROW + ch * 16);
        cp16(d,           (const char*)Qh + g);
        cp16(d + AQL_OFF, (const char*)Ql + g);
    }
#define LOAD_KV(c, s) do {                                                     \
        uint32_t st_ = sb + AST_OFF + (uint32_t)(s) * AST_SZ;                  \
        _Pragma("unroll")                                                      \
        for (int it_ = 0; it_ < 4; ++it_) {                                    \
            int idx_ = it_ * 256 + tid;                                        \
            int r_  = idx_ >> 4;                                               \
            int ch_ = idx_ & 15;                                               \
            size_t g_ = ((krow0 + (size_t)(c) * 64 + r_) * HIDDEN + hoff + ch_ * 8) * 2; \
            uint32_t d_ = st_ + (uint32_t)(r_ * SROW + ch_ * 16);              \
            cp16(d_,           (const char*)Kh + g_);                          \
            cp16(d_ + AKL_OFF, (const char*)Kl + g_);                          \
            cp16(d_ + AV_OFF,  (const char*)Vf + g_);                          \
        }                                                                      \
    } while (0)

    LOAD_KV(0, 0); CP_COMMIT();    // group 0: Q(hi+lo) + KV tile 0
    LOAD_KV(1, 1); CP_COMMIT();    // group 1: KV tile 1
    CP_WAIT1();                    // group 0 done (Q + KV0)
    __syncthreads();

    // ---- preload Q hi A-frags ----
    const int arow = lane & 15;
    const int aseg = lane >> 4;
    const uint32_t qbase = sb + (uint32_t)((wid * 16 + arow) * SROW + aseg * 16);
    uint32_t qh[8][4];
#pragma unroll
    for (int ks = 0; ks < 8; ++ks) ldsm_x4(qh[ks], qbase + ks * 32);
    const uint32_t qlbase = qbase + AQL_OFF;

    float Oacc[16][4];
#pragma unroll
    for (int nt = 0; nt < 16; ++nt)
#pragma unroll
        for (int q = 0; q < 4; ++q) Oacc[nt][q] = 0.f;
    float m0 = -1e30f, m1 = -1e30f, l0 = 0.f, l1 = 0.f;

    const int brow = ((lane >> 4) << 3) + (lane & 7);
    const int bseg = (lane >> 3) & 1;

    int stage = 0;
    for (int kt = 0; kt < NKT; ++kt) {
        __syncthreads();                    // all warps done with tile kt-1
        if (kt + 2 < NKT) {
            int s2 = stage + 2; if (s2 >= 3) s2 -= 3;
            LOAD_KV(kt + 2, s2);
        }
        CP_COMMIT();
        CP_WAIT2();                         // tile kt's data complete

        const uint32_t st = sb + AST_OFF + (uint32_t)stage * AST_SZ;

        float S[8][4];
#pragma unroll
        for (int nt = 0; nt < 8; ++nt)
#pragma unroll
            for (int q = 0; q < 4; ++q) S[nt][q] = 0.f;

#pragma unroll
        for (int ks = 0; ks < 8; ++ks) {
            uint32_t koff = (uint32_t)(brow * SROW + ks * 32 + bseg * 16);
            uint32_t kh4[4][4];
#pragma unroll
            for (int p = 0; p < 4; ++p) ldsm_x4(kh4[p], st + p * (16 * SROW) + koff);
#pragma unroll
            for (int p = 0; p < 4; ++p) {
                mma16816(S[2 * p + 0], qh[ks], kh4[p][0], kh4[p][1]);
                mma16816(S[2 * p + 1], qh[ks], kh4[p][2], kh4[p][3]);
            }
            uint32_t ql4[4];
            ldsm_x4(ql4, qlbase + ks * 32);
#pragma unroll
            for (int p = 0; p < 4; ++p) {
                mma16816(S[2 * p + 0], ql4, kh4[p][0], kh4[p][1]);
                mma16816(S[2 * p + 1], ql4, kh4[p][2], kh4[p][3]);
            }
#pragma unroll
            for (int p = 0; p < 4; ++p) {
                uint32_t kl4[4];
                ldsm_x4(kl4, st + AKL_OFF + p * (16 * SROW) + koff);
                mma16816(S[2 * p + 0], qh[ks], kl4[0], kl4[1]);
                mma16816(S[2 * p + 1], qh[ks], kl4[2], kl4[3]);
            }
        }

        // ---- online softmax ----
        float mx0 = -1e30f, mx1 = -1e30f;
#pragma unroll
        for (int nt = 0; nt < 8; ++nt) {
            mx0 = fmaxf(mx0, fmaxf(S[nt][0], S[nt][1]));
            mx1 = fmaxf(mx1, fmaxf(S[nt][2], S[nt][3]));
        }
        mx0 = fmaxf(mx0, __shfl_xor_sync(0xffffffffu, mx0, 1));
        mx0 = fmaxf(mx0, __shfl_xor_sync(0xffffffffu, mx0, 2));
        mx1 = fmaxf(mx1, __shfl_xor_sync(0xffffffffu, mx1, 1));
        mx1 = fmaxf(mx1, __shfl_xor_sync(0xffffffffu, mx1, 2));
        float mn0 = fmaxf(m0, mx0), mn1 = fmaxf(m1, mx1);
        float cf0 = __expf(scale * (m0 - mn0));
        float cf1 = __expf(scale * (m1 - mn1));
        m0 = mn0; m1 = mn1;
        float bb0 = -scale * mn0, bb1 = -scale * mn1;
        float rs0 = 0.f, rs1 = 0.f;
#pragma unroll
        for (int nt = 0; nt < 8; ++nt) {
            S[nt][0] = __expf(fmaf(S[nt][0], scale, bb0));
            S[nt][1] = __expf(fmaf(S[nt][1], scale, bb0));
            S[nt][2] = __expf(fmaf(S[nt][2], scale, bb1));
            S[nt][3] = __expf(fmaf(S[nt][3], scale, bb1));
            rs0 += S[nt][0] + S[nt][1];
            rs1 += S[nt][2] + S[nt][3];
        }
        rs0 += __shfl_xor_sync(0xffffffffu, rs0, 1);
        rs0 += __shfl_xor_sync(0xffffffffu, rs0, 2);
        rs1 += __shfl_xor_sync(0xffffffffu, rs1, 1);
        rs1 += __shfl_xor_sync(0xffffffffu, rs1, 2);
        l0 = l0 * cf0 + rs0;
        l1 = l1 * cf1 + rs1;

#pragma unroll
        for (int nt = 0; nt < 16; ++nt) {
            Oacc[nt][0] *= cf0; Oacc[nt][1] *= cf0;
            Oacc[nt][2] *= cf1; Oacc[nt][3] *= cf1;
        }
        uint32_t pa[4][4];
#pragma unroll
        for (int t = 0; t < 4; ++t) {
            pa[t][0] = pack_f16x2(S[2 * t][0],     S[2 * t][1]);
            pa[t][1] = pack_f16x2(S[2 * t][2],     S[2 * t][3]);
            pa[t][2] = pack_f16x2(S[2 * t + 1][0], S[2 * t + 1][1]);
            pa[t][3] = pack_f16x2(S[2 * t + 1][2], S[2 * t + 1][3]);
        }

        // ---- PV (fp16 x fp16 -> fp32) ----
        const uint32_t vbase = st + AV_OFF;
#pragma unroll
        for (int t = 0; t < 4; ++t) {
            uint32_t rowoff = vbase + (uint32_t)((t * 16 + (lane & 15)) * SROW + (lane >> 4) * 16);
#pragma unroll
            for (int dp = 0; dp < 8; ++dp) {
                uint32_t vb[4];
                ldsm_x4_t(vb, rowoff + dp * 32);
                mma16816h(Oacc[2 * dp + 0], pa[t], vb[0], vb[1]);
                mma16816h(Oacc[2 * dp + 1], pa[t], vb[2], vb[3]);
            }
        }
        stage = (stage == 2) ? 0 : stage + 1;
    }

    // ---- epilogue ----
    float inv0 = 1.0f / l0, inv1 = 1.0f / l1;
    int r = wid * 16 + (lane >> 2);
    size_t g0 = (qrow0 + r) * HIDDEN + hoff;
    size_t g1 = g0 + 8 * HIDDEN;
#pragma unroll
    for (int nt = 0; nt < 16; ++nt) {
        int col = nt * 8 + 2 * (lane & 3);
        float v0 = Oacc[nt][0] * inv0, v1 = Oacc[nt][1] * inv0;
        float v2 = Oacc[nt][2] * inv1, v3 = Oacc[nt][3] * inv1;
        __nv_bfloat16 h0 = __float2bfloat16(v0), h1 = __float2bfloat16(v1);
        __nv_bfloat16 h2 = __float2bfloat16(v2), h3 = __float2bfloat16(v3);
        *(__nv_bfloat162*)&Oh[g0 + col] = __halves2bfloat162(h0, h1);
        *(__nv_bfloat162*)&Oh[g1 + col] = __halves2bfloat162(h2, h3);
        *(__nv_bfloat162*)&Ol[g0 + col] = __halves2bfloat162(
            __float2bfloat16(v0 - __bfloat162float(h0)),
            __float2bfloat16(v1 - __bfloat162float(h1)));
        *(__nv_bfloat162*)&Ol[g1 + col] = __halves2bfloat162(
            __float2bfloat16(v2 - __bfloat162float(h2)),
            __float2bfloat16(v3 - __bfloat162float(h3)));
    }
}

// =====================================================================
extern "C" void kernel_launch(void* const* d_in, const int* in_sizes, int n_in,
                              void* d_out, int out_size)
{
    const float* x  = (const float*)d_in[0];
    const float* wq = (const float*)d_in[1];
    const float* wk = (const float*)d_in[2];
    const float* wv = (const float*)d_in[3];
    const float* wo = (const float*)d_in[4];
    float* out = (float*)d_out;

    __nv_bfloat16 *xh, *xl, *oh, *ol;
    __nv_bfloat16 *qbh, *qbl, *kbh, *kbl;
    __half *vf;
    __nv_bfloat16 *wqh, *wql, *wkh, *wkl, *wvh, *wvl, *woh, *wol;
    cudaGetSymbolAddress((void**)&xh, g_xh);   cudaGetSymbolAddress((void**)&xl, g_xl);
    cudaGetSymbolAddress((void**)&oh, g_oh);   cudaGetSymbolAddress((void**)&ol, g_ol);
    cudaGetSymbolAddress((void**)&qbh, g_qbh); cudaGetSymbolAddress((void**)&qbl, g_qbl);
    cudaGetSymbolAddress((void**)&kbh, g_kbh); cudaGetSymbolAddress((void**)&kbl, g_kbl);
    cudaGetSymbolAddress((void**)&vf, g_vf);
    cudaGetSymbolAddress((void**)&wqh, g_wqh); cudaGetSymbolAddress((void**)&wql, g_wql);
    cudaGetSymbolAddress((void**)&wkh, g_wkh); cudaGetSymbolAddress((void**)&wkl, g_wkl);
    cudaGetSymbolAddress((void**)&wvh, g_wvh); cudaGetSymbolAddress((void**)&wvl, g_wvl);
    cudaGetSymbolAddress((void**)&woh, g_woh); cudaGetSymbolAddress((void**)&wol, g_wol);

    const int M = MROWS;   // 4096

    cvt_all<<<24576, 256>>>((const float4*)x, (const float4*)wq, (const float4*)wk,
                            (const float4*)wv, (const float4*)wo,
                            (__nv_bfloat162*)xh,  (__nv_bfloat162*)xl,
                            (__nv_bfloat162*)wqh, (__nv_bfloat162*)wql,
                            (__nv_bfloat162*)wkh, (__nv_bfloat162*)wkl,
                            (__nv_bfloat162*)wvh, (__nv_bfloat162*)wvl,
                            (__nv_bfloat162*)woh, (__nv_bfloat162*)wol);

    cudaFuncSetAttribute(gemm_mma, cudaFuncAttributeMaxDynamicSharedMemorySize, GEMM_SMEM);
    dim3 ggrid(HIDDEN / 128, M / 128);   // (16, 32)
    gemm_mma<<<ggrid, 256, GEMM_SMEM>>>(xh, xl, wqh, wql, nullptr, qbh, qbl, nullptr, M, HIDDEN, HIDDEN);
    gemm_mma<<<ggrid, 256, GEMM_SMEM>>>(xh, xl, wkh, wkl, nullptr, kbh, kbl, nullptr, M, HIDDEN, HIDDEN);
    gemm_mma<<<ggrid, 256, GEMM_SMEM>>>(xh, xl, wvh, wvl, nullptr, nullptr, nullptr, vf, M, HIDDEN, HIDDEN);

    cudaFuncSetAttribute(attn_mma, cudaFuncAttributeMaxDynamicSharedMemorySize, ATTN_SMEM);
    attn_mma<<<dim3(BATCH * NHEADS, SEQ / QT), 256, ATTN_SMEM>>>(qbh, qbl, kbh, kbl, vf, oh, ol);

    gemm_mma<<<ggrid, 256, GEMM_SMEM>>>(oh, ol, woh, wol, out, nullptr, nullptr, nullptr, M, HIDDEN, HIDDEN);
}

// round 9
// speedup vs baseline: 3.4434x; 1.4103x over previous
#include <cuda_runtime.h>
#include <cuda_fp16.h>
#include <cstdint>

#define HIDDEN 2048
#define SEQ    2048
#define BATCH  2
#define NHEADS 16
#define HDIM   128
#define MROWS  (BATCH * SEQ)   // 4096

// ---------- scratch (all fp16) ----------
__device__ __half g_xh[MROWS * HIDDEN], g_xl[MROWS * HIDDEN];
__device__ __half g_oh[MROWS * HIDDEN], g_ol[MROWS * HIDDEN];
__device__ __half g_qbh[MROWS * HIDDEN], g_qbl[MROWS * HIDDEN];
__device__ __half g_kbh[MROWS * HIDDEN], g_kbl[MROWS * HIDDEN];
__device__ __half g_vf[MROWS * HIDDEN];
__device__ __half g_wqf[HIDDEN * HIDDEN], g_wkf[HIDDEN * HIDDEN];
__device__ __half g_wvf[HIDDEN * HIDDEN], g_wof[HIDDEN * HIDDEN];

// ---------- PTX wrappers (sm_80/90-era, valid on compute_103) ----------
__device__ __forceinline__ uint32_t smem_u32(const void* p) {
    uint32_t a;
    asm("{ .reg .u64 t; cvta.to.shared.u64 t, %1; cvt.u32.u64 %0, t; }" : "=r"(a) : "l"(p));
    return a;
}
__device__ __forceinline__ void cp16(uint32_t sdst, const void* gsrc) {
    asm volatile("cp.async.cg.shared.global [%0], [%1], 16;" :: "r"(sdst), "l"(gsrc) : "memory");
}
#define CP_COMMIT() asm volatile("cp.async.commit_group;" ::: "memory")
#define CP_WAIT1()  asm volatile("cp.async.wait_group 1;" ::: "memory")
#define CP_WAIT2()  asm volatile("cp.async.wait_group 2;" ::: "memory")
#define CP_WAIT3()  asm volatile("cp.async.wait_group 3;" ::: "memory")

__device__ __forceinline__ void ldsm_x4(uint32_t (&r)[4], uint32_t addr) {
    asm volatile("ldmatrix.sync.aligned.m8n8.x4.shared.b16 {%0,%1,%2,%3}, [%4];"
                 : "=r"(r[0]), "=r"(r[1]), "=r"(r[2]), "=r"(r[3]) : "r"(addr));
}
__device__ __forceinline__ void ldsm_x4_t(uint32_t (&r)[4], uint32_t addr) {
    asm volatile("ldmatrix.sync.aligned.m8n8.x4.trans.shared.b16 {%0,%1,%2,%3}, [%4];"
                 : "=r"(r[0]), "=r"(r[1]), "=r"(r[2]), "=r"(r[3]) : "r"(addr));
}
__device__ __forceinline__ void mma16816h(float (&d)[4], const uint32_t (&a)[4],
                                          uint32_t b0, uint32_t b1) {
    asm volatile(
        "mma.sync.aligned.m16n8k16.row.col.f32.f16.f16.f32 "
        "{%0,%1,%2,%3}, {%4,%5,%6,%7}, {%8,%9}, {%0,%1,%2,%3};"
        : "+f"(d[0]), "+f"(d[1]), "+f"(d[2]), "+f"(d[3])
        : "r"(a[0]), "r"(a[1]), "r"(a[2]), "r"(a[3]), "r"(b0), "r"(b1));
}
__device__ __forceinline__ uint32_t pack_f16x2(float lo, float hi) {
    __half2 h = __float22half2_rn(make_float2(lo, hi));
    return *(uint32_t*)&h;
}

// ---------- fused fp32 -> fp16 conversions ----------
// x -> hi/lo fp16; weights -> single fp16.
__global__ __launch_bounds__(256)
void cvt_all(const float4* __restrict__ x,  const float4* __restrict__ wq,
             const float4* __restrict__ wk, const float4* __restrict__ wv,
             const float4* __restrict__ wo,
             __half2* xh, __half2* xl,
             __half2* wqf, __half2* wkf, __half2* wvf, __half2* wof)
{
    int bid = blockIdx.x;
    if (bid < 8192) {
        size_t i = (size_t)bid * 256 + threadIdx.x;
        float4 v = x[i];
        __half hx = __float2half_rn(v.x), hy = __float2half_rn(v.y);
        __half hz = __float2half_rn(v.z), hw = __float2half_rn(v.w);
        xh[2 * i]     = __halves2half2(hx, hy);
        xh[2 * i + 1] = __halves2half2(hz, hw);
        xl[2 * i]     = __halves2half2(__float2half_rn(v.x - __half2float(hx)),
                                       __float2half_rn(v.y - __half2float(hy)));
        xl[2 * i + 1] = __halves2half2(__float2half_rn(v.z - __half2float(hz)),
                                       __float2half_rn(v.w - __half2float(hw)));
        return;
    }
    const float4* src; __half2* dst; int base;
    if      (bid < 12288) { src = wq; dst = wqf; base = bid - 8192; }
    else if (bid < 16384) { src = wk; dst = wkf; base = bid - 12288; }
    else if (bid < 20480) { src = wv; dst = wvf; base = bid - 16384; }
    else                  { src = wo; dst = wof; base = bid - 20480; }
    size_t i = (size_t)base * 256 + threadIdx.x;
    float4 v = src[i];
    dst[2 * i]     = __float22half2_rn(make_float2(v.x, v.y));
    dst[2 * i + 1] = __float22half2_rn(make_float2(v.z, v.w));
}

// =====================================================================
// 2-pass fp16 HMMA GEMM: C = (Ah+Al) @ Bh^T  (weight rounding ~2.8e-4).
// 128x128 CTA tile, 8 warps (4m x 2n), BK=32, 64B rows + XOR swizzle.
// 4-stage pipeline, one sync per chunk, loads before wait.
// grid.z selects B/output set (QKV fused). Epilogue: fp16 h/l | fp16 | fp32.
// =====================================================================
#define BK       32
#define NKCH     (HIDDEN / BK)          // 64
#define ROWB     64
#define TILE_B   (128 * ROWB)           // 8192
#define STAGE_B  (3 * TILE_B)           // 24576: Ah Al Bh
#define GEMM_SMEM (4 * STAGE_B)         // 98304

__global__ __launch_bounds__(256, 2)
void gemm2(const __half* __restrict__ Ah, const __half* __restrict__ Al,
           const __half* __restrict__ B0, const __half* __restrict__ B1,
           const __half* __restrict__ B2,
           __half* __restrict__ Ch0, __half* __restrict__ Cl0,
           __half* __restrict__ Ch1, __half* __restrict__ Cl1,
           __half* __restrict__ Cf2,
           float* __restrict__ C,
           int M, int N, int K)
{
    extern __shared__ __align__(128) char smem[];
    const uint32_t sbase = smem_u32(smem);
    const int tid  = threadIdx.x;
    const int wid  = tid >> 5;
    const int lane = tid & 31;
    const int wm   = wid & 3;
    const int wn   = wid >> 2;
    const int z    = blockIdx.z;
    const size_t brow = (size_t)blockIdx.y * 128;
    const size_t bcol = (size_t)blockIdx.x * 128;

    const __half* Bsel = (z == 0) ? B0 : (z == 1) ? B1 : B2;

    const int row = tid >> 1;
    const int sp  = (tid & 1) * 2;
    const int wmsk = (row >> 1) & 3;
    const uint32_t soff0 = (uint32_t)(row * ROWB + ((sp    ) ^ wmsk) * 16);
    const uint32_t soff1 = (uint32_t)(row * ROWB + ((sp + 1) ^ wmsk) * 16);

    const size_t Kb = (size_t)K * 2;
    const char* pAh = (const char*)Ah   + (brow + row) * Kb + sp * 16;
    const char* pAl = (const char*)Al   + (brow + row) * Kb + sp * 16;
    const char* pB  = (const char*)Bsel + (bcol + row) * Kb + sp * 16;

#define LOAD_CHUNK(c, s) do {                                    \
        uint32_t sb_ = sbase + (uint32_t)(s) * STAGE_B;          \
        size_t g_ = (size_t)(c) * 64;                            \
        cp16(sb_ + 0 * TILE_B + soff0, pAh + g_);                \
        cp16(sb_ + 0 * TILE_B + soff1, pAh + g_ + 16);           \
        cp16(sb_ + 1 * TILE_B + soff0, pAl + g_);                \
        cp16(sb_ + 1 * TILE_B + soff1, pAl + g_ + 16);           \
        cp16(sb_ + 2 * TILE_B + soff0, pB  + g_);                \
        cp16(sb_ + 2 * TILE_B + soff1, pB  + g_ + 16);           \
    } while (0)

    const int rA    = wm * 32 + (lane & 15);
    const int aSeg  = lane >> 4;
    const int maskA = (rA >> 1) & 3;
    const int rB    = wn * 64 + ((lane >> 4) << 3) + (lane & 7);
    const int bSeg  = (lane >> 3) & 1;
    const int maskB = (rB >> 1) & 3;

    float acc[2][8][4];
#pragma unroll
    for (int mt = 0; mt < 2; ++mt)
#pragma unroll
        for (int nt = 0; nt < 8; ++nt)
#pragma unroll
            for (int q = 0; q < 4; ++q) acc[mt][nt][q] = 0.f;

    LOAD_CHUNK(0, 0); CP_COMMIT();
    LOAD_CHUNK(1, 1); CP_COMMIT();
    LOAD_CHUNK(2, 2); CP_COMMIT();

    int stage = 0;
    for (int c = 0; c < NKCH; ++c) {
        __syncthreads();                        // all warps done with chunk c-1
        if (c + 3 < NKCH) LOAD_CHUNK(c + 3, (c + 3) & 3);   // stage (c-1)&3, freed
        CP_COMMIT();
        CP_WAIT3();                             // chunk c complete

        const uint32_t sb = sbase + (uint32_t)stage * STAGE_B;

#pragma unroll
        for (int k16 = 0; k16 < 2; ++k16) {
            uint32_t ah[2][4], al[2][4];
#pragma unroll
            for (int mt = 0; mt < 2; ++mt) {
                uint32_t byteoff = (uint32_t)((rA + mt * 16) * ROWB +
                                              ((2 * k16 + aSeg) ^ maskA) * 16);
                ldsm_x4(ah[mt], sb + 0 * TILE_B + byteoff);
                ldsm_x4(al[mt], sb + 1 * TILE_B + byteoff);
            }
            uint32_t bh[4][4];
#pragma unroll
            for (int np = 0; np < 4; ++np) {
                uint32_t byteoff = (uint32_t)((rB + np * 16) * ROWB +
                                              ((2 * k16 + bSeg) ^ maskB) * 16);
                ldsm_x4(bh[np], sb + 2 * TILE_B + byteoff);
            }
            // pass 1: Ah * Bh
#pragma unroll
            for (int np = 0; np < 4; ++np)
#pragma unroll
                for (int mt = 0; mt < 2; ++mt) {
                    mma16816h(acc[mt][2 * np + 0], ah[mt], bh[np][0], bh[np][1]);
                    mma16816h(acc[mt][2 * np + 1], ah[mt], bh[np][2], bh[np][3]);
                }
            // pass 2: Al * Bh
#pragma unroll
            for (int np = 0; np < 4; ++np)
#pragma unroll
                for (int mt = 0; mt < 2; ++mt) {
                    mma16816h(acc[mt][2 * np + 0], al[mt], bh[np][0], bh[np][1]);
                    mma16816h(acc[mt][2 * np + 1], al[mt], bh[np][2], bh[np][3]);
                }
        }
        stage = (stage + 1) & 3;
    }

    __half* Ch = (z == 0) ? Ch0 : Ch1;
    __half* Cl = (z == 0) ? Cl0 : Cl1;
#pragma unroll
    for (int mt = 0; mt < 2; ++mt) {
        size_t r0 = brow + wm * 32 + mt * 16 + (lane >> 2);
#pragma unroll
        for (int nt = 0; nt < 8; ++nt) {
            size_t col = bcol + wn * 64 + nt * 8 + 2 * (lane & 3);
            if (C) {
                *(float2*)&C[r0 * (size_t)N + col]       = make_float2(acc[mt][nt][0], acc[mt][nt][1]);
                *(float2*)&C[(r0 + 8) * (size_t)N + col] = make_float2(acc[mt][nt][2], acc[mt][nt][3]);
            } else if (z == 2) {
#pragma unroll
                for (int hf = 0; hf < 2; ++hf) {
                    size_t idx = (r0 + 8 * hf) * (size_t)N + col;
                    *(__half2*)&Cf2[idx] = __float22half2_rn(
                        make_float2(acc[mt][nt][2 * hf], acc[mt][nt][2 * hf + 1]));
                }
            } else {
#pragma unroll
                for (int hf = 0; hf < 2; ++hf) {
                    float v0 = acc[mt][nt][2 * hf + 0];
                    float v1 = acc[mt][nt][2 * hf + 1];
                    __half h0 = __float2half_rn(v0);
                    __half h1 = __float2half_rn(v1);
                    size_t idx = (r0 + 8 * hf) * (size_t)N + col;
                    *(__half2*)&Ch[idx] = __halves2half2(h0, h1);
                    *(__half2*)&Cl[idx] = __halves2half2(
                        __float2half_rn(v0 - __half2float(h0)),
                        __float2half_rn(v1 - __half2float(h1)));
                }
            }
        }
    }
}

// =====================================================================
// FlashAttention-2 on fp16 HMMA. Scores: 3-pass hi/lo fp16 (near-exact).
// PV: fp16 P and V, single pass. 3-stage KV pipeline, one sync per tile.
// smem: Qh @0 | Ql @34816 | stage s @69632+s*52224: Kh | Kl(+17408) | V(+34816)
// =====================================================================
#define QT        128
#define SROW      272
#define AQL_OFF   34816
#define AST_OFF   69632
#define AST_SZ    52224
#define AKL_OFF   17408
#define AV_OFF    34816
#define ATTN_SMEM 226304
#define NKT       (SEQ / 64)   // 32

__global__ __launch_bounds__(256, 1)
void attn_mma(const __half* __restrict__ Qh, const __half* __restrict__ Ql,
              const __half* __restrict__ Kh, const __half* __restrict__ Kl,
              const __half* __restrict__ Vf,
              __half* __restrict__ Oh, __half* __restrict__ Ol)
{
    extern __shared__ __align__(128) char smem[];
    const uint32_t sb = smem_u32(smem);
    const int tid  = threadIdx.x;
    const int wid  = tid >> 5;
    const int lane = tid & 31;
    const int b    = blockIdx.x >> 4;
    const int h    = blockIdx.x & 15;
    const int qt   = blockIdx.y;

    const float scale = 0.08838834764831843f;   // 1/sqrt(128)
    const size_t hoff  = (size_t)h * HDIM;
    const size_t qrow0 = (size_t)b * SEQ + (size_t)qt * QT;
    const size_t krow0 = (size_t)b * SEQ;

#pragma unroll
    for (int it = 0; it < 8; ++it) {
        int idx = it * 256 + tid;
        int r   = idx >> 4;
        int ch  = idx & 15;
        size_t g = ((qrow0 + r) * HIDDEN + hoff + ch * 8) * 2;
        uint32_t d = sb + (uint32_t)(r * SROW + ch * 16);
        cp16(d,           (const char*)Qh + g);
        cp16(d + AQL_OFF, (const char*)Ql + g);
    }
#define LOAD_KV(c, s) do {                                                     \
        uint32_t st_ = sb + AST_OFF + (uint32_t)(s) * AST_SZ;                  \
        _Pragma("unroll")                                                      \
        for (int it_ = 0; it_ < 4; ++it_) {                                    \
            int idx_ = it_ * 256 + tid;                                        \
            int r_  = idx_ >> 4;                                               \
            int ch_ = idx_ & 15;                                               \
            size_t g_ = ((krow0 + (size_t)(c) * 64 + r_) * HIDDEN + hoff + ch_ * 8) * 2; \
            uint32_t d_ = st_ + (uint32_t)(r_ * SROW + ch_ * 16);              \
            cp16(d_,           (const char*)Kh + g_);                          \
            cp16(d_ + AKL_OFF, (const char*)Kl + g_);                          \
            cp16(d_ + AV_OFF,  (const char*)Vf + g_);                          \
        }                                                                      \
    } while (0)

    LOAD_KV(0, 0); CP_COMMIT();
    LOAD_KV(1, 1); CP_COMMIT();
    CP_WAIT1();
    __syncthreads();

    const int arow = lane & 15;
    const int aseg = lane >> 4;
    const uint32_t qbase = sb + (uint32_t)((wid * 16 + arow) * SROW + aseg * 16);
    uint32_t qh[8][4];
#pragma unroll
    for (int ks = 0; ks < 8; ++ks) ldsm_x4(qh[ks], qbase + ks * 32);
    const uint32_t qlbase = qbase + AQL_OFF;

    float Oacc[16][4];
#pragma unroll
    for (int nt = 0; nt < 16; ++nt)
#pragma unroll
        for (int q = 0; q < 4; ++q) Oacc[nt][q] = 0.f;
    float m0 = -1e30f, m1 = -1e30f, l0 = 0.f, l1 = 0.f;

    const int brow = ((lane >> 4) << 3) + (lane & 7);
    const int bseg = (lane >> 3) & 1;

    int stage = 0;
    for (int kt = 0; kt < NKT; ++kt) {
        __syncthreads();
        if (kt + 2 < NKT) {
            int s2 = stage + 2; if (s2 >= 3) s2 -= 3;
            LOAD_KV(kt + 2, s2);
        }
        CP_COMMIT();
        CP_WAIT2();

        const uint32_t st = sb + AST_OFF + (uint32_t)stage * AST_SZ;

        float S[8][4];
#pragma unroll
        for (int nt = 0; nt < 8; ++nt)
#pragma unroll
            for (int q = 0; q < 4; ++q) S[nt][q] = 0.f;

#pragma unroll
        for (int ks = 0; ks < 8; ++ks) {
            uint32_t koff = (uint32_t)(brow * SROW + ks * 32 + bseg * 16);
            uint32_t kh4[4][4];
#pragma unroll
            for (int p = 0; p < 4; ++p) ldsm_x4(kh4[p], st + p * (16 * SROW) + koff);
#pragma unroll
            for (int p = 0; p < 4; ++p) {
                mma16816h(S[2 * p + 0], qh[ks], kh4[p][0], kh4[p][1]);
                mma16816h(S[2 * p + 1], qh[ks], kh4[p][2], kh4[p][3]);
            }
            uint32_t ql4[4];
            ldsm_x4(ql4, qlbase + ks * 32);
#pragma unroll
            for (int p = 0; p < 4; ++p) {
                mma16816h(S[2 * p + 0], ql4, kh4[p][0], kh4[p][1]);
                mma16816h(S[2 * p + 1], ql4, kh4[p][2], kh4[p][3]);
            }
#pragma unroll
            for (int p = 0; p < 4; ++p) {
                uint32_t kl4[4];
                ldsm_x4(kl4, st + AKL_OFF + p * (16 * SROW) + koff);
                mma16816h(S[2 * p + 0], qh[ks], kl4[0], kl4[1]);
                mma16816h(S[2 * p + 1], qh[ks], kl4[2], kl4[3]);
            }
        }

        // ---- online softmax ----
        float mx0 = -1e30f, mx1 = -1e30f;
#pragma unroll
        for (int nt = 0; nt < 8; ++nt) {
            mx0 = fmaxf(mx0, fmaxf(S[nt][0], S[nt][1]));
            mx1 = fmaxf(mx1, fmaxf(S[nt][2], S[nt][3]));
        }
        mx0 = fmaxf(mx0, __shfl_xor_sync(0xffffffffu, mx0, 1));
        mx0 = fmaxf(mx0, __shfl_xor_sync(0xffffffffu, mx0, 2));
        mx1 = fmaxf(mx1, __shfl_xor_sync(0xffffffffu, mx1, 1));
        mx1 = fmaxf(mx1, __shfl_xor_sync(0xffffffffu, mx1, 2));
        float mn0 = fmaxf(m0, mx0), mn1 = fmaxf(m1, mx1);
        float cf0 = __expf(scale * (m0 - mn0));
        float cf1 = __expf(scale * (m1 - mn1));
        m0 = mn0; m1 = mn1;
        float bb0 = -scale * mn0, bb1 = -scale * mn1;
        float rs0 = 0.f, rs1 = 0.f;
#pragma unroll
        for (int nt = 0; nt < 8; ++nt) {
            S[nt][0] = __expf(fmaf(S[nt][0], scale, bb0));
            S[nt][1] = __expf(fmaf(S[nt][1], scale, bb0));
            S[nt][2] = __expf(fmaf(S[nt][2], scale, bb1));
            S[nt][3] = __expf(fmaf(S[nt][3], scale, bb1));
            rs0 += S[nt][0] + S[nt][1];
            rs1 += S[nt][2] + S[nt][3];
        }
        rs0 += __shfl_xor_sync(0xffffffffu, rs0, 1);
        rs0 += __shfl_xor_sync(0xffffffffu, rs0, 2);
        rs1 += __shfl_xor_sync(0xffffffffu, rs1, 1);
        rs1 += __shfl_xor_sync(0xffffffffu, rs1, 2);
        l0 = l0 * cf0 + rs0;
        l1 = l1 * cf1 + rs1;

#pragma unroll
        for (int nt = 0; nt < 16; ++nt) {
            Oacc[nt][0] *= cf0; Oacc[nt][1] *= cf0;
            Oacc[nt][2] *= cf1; Oacc[nt][3] *= cf1;
        }
        uint32_t pa[4][4];
#pragma unroll
        for (int t = 0; t < 4; ++t) {
            pa[t][0] = pack_f16x2(S[2 * t][0],     S[2 * t][1]);
            pa[t][1] = pack_f16x2(S[2 * t][2],     S[2 * t][3]);
            pa[t][2] = pack_f16x2(S[2 * t + 1][0], S[2 * t + 1][1]);
            pa[t][3] = pack_f16x2(S[2 * t + 1][2], S[2 * t + 1][3]);
        }

        // ---- PV (fp16 x fp16 -> fp32) ----
        const uint32_t vbase = st + AV_OFF;
#pragma unroll
        for (int t = 0; t < 4; ++t) {
            uint32_t rowoff = vbase + (uint32_t)((t * 16 + (lane & 15)) * SROW + (lane >> 4) * 16);
#pragma unroll
            for (int dp = 0; dp < 8; ++dp) {
                uint32_t vb[4];
                ldsm_x4_t(vb, rowoff + dp * 32);
                mma16816h(Oacc[2 * dp + 0], pa[t], vb[0], vb[1]);
                mma16816h(Oacc[2 * dp + 1], pa[t], vb[2], vb[3]);
            }
        }
        stage = (stage == 2) ? 0 : stage + 1;
    }

    // ---- epilogue: normalize, write fp16 hi/lo ----
    float inv0 = 1.0f / l0, inv1 = 1.0f / l1;
    int r = wid * 16 + (lane >> 2);
    size_t g0 = (qrow0 + r) * HIDDEN + hoff;
    size_t g1 = g0 + 8 * HIDDEN;
#pragma unroll
    for (int nt = 0; nt < 16; ++nt) {
        int col = nt * 8 + 2 * (lane & 3);
        float v0 = Oacc[nt][0] * inv0, v1 = Oacc[nt][1] * inv0;
        float v2 = Oacc[nt][2] * inv1, v3 = Oacc[nt][3] * inv1;
        __half h0 = __float2half_rn(v0), h1 = __float2half_rn(v1);
        __half h2 = __float2half_rn(v2), h3 = __float2half_rn(v3);
        *(__half2*)&Oh[g0 + col] = __halves2half2(h0, h1);
        *(__half2*)&Oh[g1 + col] = __halves2half2(h2, h3);
        *(__half2*)&Ol[g0 + col] = __halves2half2(
            __float2half_rn(v0 - __half2float(h0)),
            __float2half_rn(v1 - __half2float(h1)));
        *(__half2*)&Ol[g1 + col] = __halves2half2(
            __float2half_rn(v2 - __half2float(h2)),
            __float2half_rn(v3 - __half2float(h3)));
    }
}

// =====================================================================
extern "C" void kernel_launch(void* const* d_in, const int* in_sizes, int n_in,
                              void* d_out, int out_size)
{
    const float* x  = (const float*)d_in[0];
    const float* wq = (const float*)d_in[1];
    const float* wk = (const float*)d_in[2];
    const float* wv = (const float*)d_in[3];
    const float* wo = (const float*)d_in[4];
    float* out = (float*)d_out;

    __half *xh, *xl, *oh, *ol, *qbh, *qbl, *kbh, *kbl, *vf;
    __half *wqf, *wkf, *wvf, *wof;
    cudaGetSymbolAddress((void**)&xh, g_xh);   cudaGetSymbolAddress((void**)&xl, g_xl);
    cudaGetSymbolAddress((void**)&oh, g_oh);   cudaGetSymbolAddress((void**)&ol, g_ol);
    cudaGetSymbolAddress((void**)&qbh, g_qbh); cudaGetSymbolAddress((void**)&qbl, g_qbl);
    cudaGetSymbolAddress((void**)&kbh, g_kbh); cudaGetSymbolAddress((void**)&kbl, g_kbl);
    cudaGetSymbolAddress((void**)&vf, g_vf);
    cudaGetSymbolAddress((void**)&wqf, g_wqf); cudaGetSymbolAddress((void**)&wkf, g_wkf);
    cudaGetSymbolAddress((void**)&wvf, g_wvf); cudaGetSymbolAddress((void**)&wof, g_wof);

    const int M = MROWS;   // 4096

    cvt_all<<<24576, 256>>>((const float4*)x, (const float4*)wq, (const float4*)wk,
                            (const float4*)wv, (const float4*)wo,
                            (__half2*)xh, (__half2*)xl,
                            (__half2*)wqf, (__half2*)wkf, (__half2*)wvf, (__half2*)wof);

    cudaFuncSetAttribute(gemm2, cudaFuncAttributeMaxDynamicSharedMemorySize, GEMM_SMEM);
    // fused QKV: z=0 -> Q (h/l), z=1 -> K (h/l), z=2 -> V (single fp16)
    gemm2<<<dim3(HIDDEN / 128, M / 128, 3), 256, GEMM_SMEM>>>(
        xh, xl, wqf, wkf, wvf, qbh, qbl, kbh, kbl, vf, nullptr, M, HIDDEN, HIDDEN);

    cudaFuncSetAttribute(attn_mma, cudaFuncAttributeMaxDynamicSharedMemorySize, ATTN_SMEM);
    attn_mma<<<dim3(BATCH * NHEADS, SEQ / QT), 256, ATTN_SMEM>>>(qbh, qbl, kbh, kbl, vf, oh, ol);

    // output projection: fp32 out
    gemm2<<<dim3(HIDDEN / 128, M / 128, 1), 256, GEMM_SMEM>>>(
        oh, ol, wof, wof, wof, nullptr, nullptr, nullptr, nullptr, nullptr, out, M, HIDDEN, HIDDEN);
}

// round 10
// speedup vs baseline: 3.9401x; 1.1442x over previous
#include <cuda_runtime.h>
#include <cuda_fp16.h>
#include <cstdint>

#define HIDDEN 2048
#define SEQ    2048
#define BATCH  2
#define NHEADS 16
#define HDIM   128
#define MROWS  (BATCH * SEQ)   // 4096

// ---------- scratch (all fp16) ----------
__device__ __half g_xh[MROWS * HIDDEN], g_xl[MROWS * HIDDEN];
__device__ __half g_oh[MROWS * HIDDEN];
__device__ __half g_qbh[MROWS * HIDDEN], g_qbl[MROWS * HIDDEN];
__device__ __half g_kbh[MROWS * HIDDEN], g_kbl[MROWS * HIDDEN];
__device__ __half g_vf[MROWS * HIDDEN];
__device__ __half g_wqf[HIDDEN * HIDDEN], g_wkf[HIDDEN * HIDDEN];
__device__ __half g_wvf[HIDDEN * HIDDEN], g_wof[HIDDEN * HIDDEN];

// ---------- PTX wrappers (sm_80/90-era, valid on compute_103) ----------
__device__ __forceinline__ uint32_t smem_u32(const void* p) {
    uint32_t a;
    asm("{ .reg .u64 t; cvta.to.shared.u64 t, %1; cvt.u32.u64 %0, t; }" : "=r"(a) : "l"(p));
    return a;
}
__device__ __forceinline__ void cp16(uint32_t sdst, const void* gsrc) {
    asm volatile("cp.async.cg.shared.global [%0], [%1], 16;" :: "r"(sdst), "l"(gsrc) : "memory");
}
#define CP_COMMIT() asm volatile("cp.async.commit_group;" ::: "memory")
#define CP_WAIT1()  asm volatile("cp.async.wait_group 1;" ::: "memory")
#define CP_WAIT2()  asm volatile("cp.async.wait_group 2;" ::: "memory")
#define CP_WAIT3()  asm volatile("cp.async.wait_group 3;" ::: "memory")

__device__ __forceinline__ void ldsm_x4(uint32_t (&r)[4], uint32_t addr) {
    asm volatile("ldmatrix.sync.aligned.m8n8.x4.shared.b16 {%0,%1,%2,%3}, [%4];"
                 : "=r"(r[0]), "=r"(r[1]), "=r"(r[2]), "=r"(r[3]) : "r"(addr));
}
__device__ __forceinline__ void ldsm_x4_t(uint32_t (&r)[4], uint32_t addr) {
    asm volatile("ldmatrix.sync.aligned.m8n8.x4.trans.shared.b16 {%0,%1,%2,%3}, [%4];"
                 : "=r"(r[0]), "=r"(r[1]), "=r"(r[2]), "=r"(r[3]) : "r"(addr));
}
__device__ __forceinline__ void mma16816h(float (&d)[4], const uint32_t (&a)[4],
                                          uint32_t b0, uint32_t b1) {
    asm volatile(
        "mma.sync.aligned.m16n8k16.row.col.f32.f16.f16.f32 "
        "{%0,%1,%2,%3}, {%4,%5,%6,%7}, {%8,%9}, {%0,%1,%2,%3};"
        : "+f"(d[0]), "+f"(d[1]), "+f"(d[2]), "+f"(d[3])
        : "r"(a[0]), "r"(a[1]), "r"(a[2]), "r"(a[3]), "r"(b0), "r"(b1));
}
__device__ __forceinline__ uint32_t pack_f16x2(float lo, float hi) {
    __half2 h = __float22half2_rn(make_float2(lo, hi));
    return *(uint32_t*)&h;
}

// ---------- fused fp32 -> fp16 conversions ----------
__global__ __launch_bounds__(256)
void cvt_all(const float4* __restrict__ x,  const float4* __restrict__ wq,
             const float4* __restrict__ wk, const float4* __restrict__ wv,
             const float4* __restrict__ wo,
             __half2* xh, __half2* xl,
             __half2* wqf, __half2* wkf, __half2* wvf, __half2* wof)
{
    int bid = blockIdx.x;
    if (bid < 8192) {
        size_t i = (size_t)bid * 256 + threadIdx.x;
        float4 v = x[i];
        __half hx = __float2half_rn(v.x), hy = __float2half_rn(v.y);
        __half hz = __float2half_rn(v.z), hw = __float2half_rn(v.w);
        xh[2 * i]     = __halves2half2(hx, hy);
        xh[2 * i + 1] = __halves2half2(hz, hw);
        xl[2 * i]     = __halves2half2(__float2half_rn(v.x - __half2float(hx)),
                                       __float2half_rn(v.y - __half2float(hy)));
        xl[2 * i + 1] = __halves2half2(__float2half_rn(v.z - __half2float(hz)),
                                       __float2half_rn(v.w - __half2float(hw)));
        return;
    }
    const float4* src; __half2* dst; int base;
    if      (bid < 12288) { src = wq; dst = wqf; base = bid - 8192; }
    else if (bid < 16384) { src = wk; dst = wkf; base = bid - 12288; }
    else if (bid < 20480) { src = wv; dst = wvf; base = bid - 16384; }
    else                  { src = wo; dst = wof; base = bid - 20480; }
    size_t i = (size_t)base * 256 + threadIdx.x;
    float4 v = src[i];
    dst[2 * i]     = __float22half2_rn(make_float2(v.x, v.y));
    dst[2 * i + 1] = __float22half2_rn(make_float2(v.z, v.w));
}

// =====================================================================
// fp16 HMMA GEMM: C = (Ah [+ Al]) @ B^T.  onepass_mask bit z => skip Al.
// 128x128 CTA tile, 8 warps (4m x 2n), BK=32, 64B rows + XOR swizzle.
// 4-stage pipeline, one sync per chunk, loads before wait.
// grid.z selects B/output set (QKV fused). Epilogue: fp16 h/l | fp16 | fp32.
// =====================================================================
#define BK       32
#define NKCH     (HIDDEN / BK)          // 64
#define ROWB     64
#define TILE_B   (128 * ROWB)           // 8192
#define STAGE_B  (3 * TILE_B)           // 24576: Ah Al B
#define GEMM_SMEM (4 * STAGE_B)         // 98304

__global__ __launch_bounds__(256, 2)
void gemm2(const __half* __restrict__ Ah, const __half* __restrict__ Al,
           const __half* __restrict__ B0, const __half* __restrict__ B1,
           const __half* __restrict__ B2,
           __half* __restrict__ Ch0, __half* __restrict__ Cl0,
           __half* __restrict__ Ch1, __half* __restrict__ Cl1,
           __half* __restrict__ Cf2,
           float* __restrict__ C,
           int onepass_mask,
           int M, int N, int K)
{
    extern __shared__ __align__(128) char smem[];
    const uint32_t sbase = smem_u32(smem);
    const int tid  = threadIdx.x;
    const int wid  = tid >> 5;
    const int lane = tid & 31;
    const int wm   = wid & 3;
    const int wn   = wid >> 2;
    const int z    = blockIdx.z;
    const bool two = !((onepass_mask >> z) & 1);
    const size_t brow = (size_t)blockIdx.y * 128;
    const size_t bcol = (size_t)blockIdx.x * 128;

    const __half* Bsel = (z == 0) ? B0 : (z == 1) ? B1 : B2;

    const int row = tid >> 1;
    const int sp  = (tid & 1) * 2;
    const int wmsk = (row >> 1) & 3;
    const uint32_t soff0 = (uint32_t)(row * ROWB + ((sp    ) ^ wmsk) * 16);
    const uint32_t soff1 = (uint32_t)(row * ROWB + ((sp + 1) ^ wmsk) * 16);

    const size_t Kb = (size_t)K * 2;
    const char* pAh = (const char*)Ah   + (brow + row) * Kb + sp * 16;
    const char* pAl = (const char*)Al   + (brow + row) * Kb + sp * 16;
    const char* pB  = (const char*)Bsel + (bcol + row) * Kb + sp * 16;

#define LOAD_CHUNK(c, s) do {                                    \
        uint32_t sb_ = sbase + (uint32_t)(s) * STAGE_B;          \
        size_t g_ = (size_t)(c) * 64;                            \
        cp16(sb_ + 0 * TILE_B + soff0, pAh + g_);                \
        cp16(sb_ + 0 * TILE_B + soff1, pAh + g_ + 16);           \
        if (two) {                                               \
            cp16(sb_ + 1 * TILE_B + soff0, pAl + g_);            \
            cp16(sb_ + 1 * TILE_B + soff1, pAl + g_ + 16);       \
        }                                                        \
        cp16(sb_ + 2 * TILE_B + soff0, pB  + g_);                \
        cp16(sb_ + 2 * TILE_B + soff1, pB  + g_ + 16);           \
    } while (0)

    const int rA    = wm * 32 + (lane & 15);
    const int aSeg  = lane >> 4;
    const int maskA = (rA >> 1) & 3;
    const int rB    = wn * 64 + ((lane >> 4) << 3) + (lane & 7);
    const int bSeg  = (lane >> 3) & 1;
    const int maskB = (rB >> 1) & 3;

    float acc[2][8][4];
#pragma unroll
    for (int mt = 0; mt < 2; ++mt)
#pragma unroll
        for (int nt = 0; nt < 8; ++nt)
#pragma unroll
            for (int q = 0; q < 4; ++q) acc[mt][nt][q] = 0.f;

    LOAD_CHUNK(0, 0); CP_COMMIT();
    LOAD_CHUNK(1, 1); CP_COMMIT();
    LOAD_CHUNK(2, 2); CP_COMMIT();

    int stage = 0;
    for (int c = 0; c < NKCH; ++c) {
        __syncthreads();                        // all warps done with chunk c-1
        if (c + 3 < NKCH) LOAD_CHUNK(c + 3, (c + 3) & 3);
        CP_COMMIT();
        CP_WAIT3();                             // chunk c complete

        const uint32_t sb = sbase + (uint32_t)stage * STAGE_B;

#pragma unroll
        for (int k16 = 0; k16 < 2; ++k16) {
            uint32_t ah[2][4];
#pragma unroll
            for (int mt = 0; mt < 2; ++mt) {
                uint32_t byteoff = (uint32_t)((rA + mt * 16) * ROWB +
                                              ((2 * k16 + aSeg) ^ maskA) * 16);
                ldsm_x4(ah[mt], sb + 0 * TILE_B + byteoff);
            }
            uint32_t bh[4][4];
#pragma unroll
            for (int np = 0; np < 4; ++np) {
                uint32_t byteoff = (uint32_t)((rB + np * 16) * ROWB +
                                              ((2 * k16 + bSeg) ^ maskB) * 16);
                ldsm_x4(bh[np], sb + 2 * TILE_B + byteoff);
            }
            // pass 1: Ah * B
#pragma unroll
            for (int np = 0; np < 4; ++np)
#pragma unroll
                for (int mt = 0; mt < 2; ++mt) {
                    mma16816h(acc[mt][2 * np + 0], ah[mt], bh[np][0], bh[np][1]);
                    mma16816h(acc[mt][2 * np + 1], ah[mt], bh[np][2], bh[np][3]);
                }
            // pass 2: Al * B (skipped for one-pass outputs)
            if (two) {
                uint32_t al[2][4];
#pragma unroll
                for (int mt = 0; mt < 2; ++mt) {
                    uint32_t byteoff = (uint32_t)((rA + mt * 16) * ROWB +
                                                  ((2 * k16 + aSeg) ^ maskA) * 16);
                    ldsm_x4(al[mt], sb + 1 * TILE_B + byteoff);
                }
#pragma unroll
                for (int np = 0; np < 4; ++np)
#pragma unroll
                    for (int mt = 0; mt < 2; ++mt) {
                        mma16816h(acc[mt][2 * np + 0], al[mt], bh[np][0], bh[np][1]);
                        mma16816h(acc[mt][2 * np + 1], al[mt], bh[np][2], bh[np][3]);
                    }
            }
        }
        stage = (stage + 1) & 3;
    }

    __half* Ch = (z == 0) ? Ch0 : Ch1;
    __half* Cl = (z == 0) ? Cl0 : Cl1;
#pragma unroll
    for (int mt = 0; mt < 2; ++mt) {
        size_t r0 = brow + wm * 32 + mt * 16 + (lane >> 2);
#pragma unroll
        for (int nt = 0; nt < 8; ++nt) {
            size_t col = bcol + wn * 64 + nt * 8 + 2 * (lane & 3);
            if (C) {
                *(float2*)&C[r0 * (size_t)N + col]       = make_float2(acc[mt][nt][0], acc[mt][nt][1]);
                *(float2*)&C[(r0 + 8) * (size_t)N + col] = make_float2(acc[mt][nt][2], acc[mt][nt][3]);
            } else if (z == 2) {
#pragma unroll
                for (int hf = 0; hf < 2; ++hf) {
                    size_t idx = (r0 + 8 * hf) * (size_t)N + col;
                    *(__half2*)&Cf2[idx] = __float22half2_rn(
                        make_float2(acc[mt][nt][2 * hf], acc[mt][nt][2 * hf + 1]));
                }
            } else {
#pragma unroll
                for (int hf = 0; hf < 2; ++hf) {
                    float v0 = acc[mt][nt][2 * hf + 0];
                    float v1 = acc[mt][nt][2 * hf + 1];
                    __half h0 = __float2half_rn(v0);
                    __half h1 = __float2half_rn(v1);
                    size_t idx = (r0 + 8 * hf) * (size_t)N + col;
                    *(__half2*)&Ch[idx] = __halves2half2(h0, h1);
                    *(__half2*)&Cl[idx] = __halves2half2(
                        __float2half_rn(v0 - __half2float(h0)),
                        __float2half_rn(v1 - __half2float(h1)));
                }
            }
        }
    }
}

// =====================================================================
// FlashAttention-2 on fp16 HMMA. Scores: 3-pass hi/lo fp16 (near-exact).
// PV: fp16 P and V, single pass. 3-stage KV pipeline, one sync per tile.
// O written as single fp16 (Oh only).
// =====================================================================
#define QT        128
#define SROW      272
#define AQL_OFF   34816
#define AST_OFF   69632
#define AST_SZ    52224
#define AKL_OFF   17408
#define AV_OFF    34816
#define ATTN_SMEM 226304
#define NKT       (SEQ / 64)   // 32

__global__ __launch_bounds__(256, 1)
void attn_mma(const __half* __restrict__ Qh, const __half* __restrict__ Ql,
              const __half* __restrict__ Kh, const __half* __restrict__ Kl,
              const __half* __restrict__ Vf,
              __half* __restrict__ Oh)
{
    extern __shared__ __align__(128) char smem[];
    const uint32_t sb = smem_u32(smem);
    const int tid  = threadIdx.x;
    const int wid  = tid >> 5;
    const int lane = tid & 31;
    const int b    = blockIdx.x >> 4;
    const int h    = blockIdx.x & 15;
    const int qt   = blockIdx.y;

    const float scale = 0.08838834764831843f;   // 1/sqrt(128)
    const size_t hoff  = (size_t)h * HDIM;
    const size_t qrow0 = (size_t)b * SEQ + (size_t)qt * QT;
    const size_t krow0 = (size_t)b * SEQ;

#pragma unroll
    for (int it = 0; it < 8; ++it) {
        int idx = it * 256 + tid;
        int r   = idx >> 4;
        int ch  = idx & 15;
        size_t g = ((qrow0 + r) * HIDDEN + hoff + ch * 8) * 2;
        uint32_t d = sb + (uint32_t)(r * SROW + ch * 16);
        cp16(d,           (const char*)Qh + g);
        cp16(d + AQL_OFF, (const char*)Ql + g);
    }
#define LOAD_KV(c, s) do {                                                     \
        uint32_t st_ = sb + AST_OFF + (uint32_t)(s) * AST_SZ;                  \
        _Pragma("unroll")                                                      \
        for (int it_ = 0; it_ < 4; ++it_) {                                    \
            int idx_ = it_ * 256 + tid;                                        \
            int r_  = idx_ >> 4;                                               \
            int ch_ = idx_ & 15;                                               \
            size_t g_ = ((krow0 + (size_t)(c) * 64 + r_) * HIDDEN + hoff + ch_ * 8) * 2; \
            uint32_t d_ = st_ + (uint32_t)(r_ * SROW + ch_ * 16);              \
            cp16(d_,           (const char*)Kh + g_);                          \
            cp16(d_ + AKL_OFF, (const char*)Kl + g_);                          \
            cp16(d_ + AV_OFF,  (const char*)Vf + g_);                          \
        }                                                                      \
    } while (0)

    LOAD_KV(0, 0); CP_COMMIT();
    LOAD_KV(1, 1); CP_COMMIT();
    CP_WAIT1();
    __syncthreads();

    const int arow = lane & 15;
    const int aseg = lane >> 4;
    const uint32_t qbase = sb + (uint32_t)((wid * 16 + arow) * SROW + aseg * 16);
    uint32_t qh[8][4];
#pragma unroll
    for (int ks = 0; ks < 8; ++ks) ldsm_x4(qh[ks], qbase + ks * 32);
    const uint32_t qlbase = qbase + AQL_OFF;

    float Oacc[16][4];
#pragma unroll
    for (int nt = 0; nt < 16; ++nt)
#pragma unroll
        for (int q = 0; q < 4; ++q) Oacc[nt][q] = 0.f;
    float m0 = -1e30f, m1 = -1e30f, l0 = 0.f, l1 = 0.f;

    const int brow = ((lane >> 4) << 3) + (lane & 7);
    const int bseg = (lane >> 3) & 1;

    int stage = 0;
    for (int kt = 0; kt < NKT; ++kt) {
        __syncthreads();
        if (kt + 2 < NKT) {
            int s2 = stage + 2; if (s2 >= 3) s2 -= 3;
            LOAD_KV(kt + 2, s2);
        }
        CP_COMMIT();
        CP_WAIT2();

        const uint32_t st = sb + AST_OFF + (uint32_t)stage * AST_SZ;

        float S[8][4];
#pragma unroll
        for (int nt = 0; nt < 8; ++nt)
#pragma unroll
            for (int q = 0; q < 4; ++q) S[nt][q] = 0.f;

#pragma unroll
        for (int ks = 0; ks < 8; ++ks) {
            uint32_t koff = (uint32_t)(brow * SROW + ks * 32 + bseg * 16);
            uint32_t kh4[4][4];
#pragma unroll
            for (int p = 0; p < 4; ++p) ldsm_x4(kh4[p], st + p * (16 * SROW) + koff);
#pragma unroll
            for (int p = 0; p < 4; ++p) {
                mma16816h(S[2 * p + 0], qh[ks], kh4[p][0], kh4[p][1]);
                mma16816h(S[2 * p + 1], qh[ks], kh4[p][2], kh4[p][3]);
            }
            uint32_t ql4[4];
            ldsm_x4(ql4, qlbase + ks * 32);
#pragma unroll
            for (int p = 0; p < 4; ++p) {
                mma16816h(S[2 * p + 0], ql4, kh4[p][0], kh4[p][1]);
                mma16816h(S[2 * p + 1], ql4, kh4[p][2], kh4[p][3]);
            }
#pragma unroll
            for (int p = 0; p < 4; ++p) {
                uint32_t kl4[4];
                ldsm_x4(kl4, st + AKL_OFF + p * (16 * SROW) + koff);
                mma16816h(S[2 * p + 0], qh[ks], kl4[0], kl4[1]);
                mma16816h(S[2 * p + 1], qh[ks], kl4[2], kl4[3]);
            }
        }

        // ---- online softmax ----
        float mx0 = -1e30f, mx1 = -1e30f;
#pragma unroll
        for (int nt = 0; nt < 8; ++nt) {
            mx0 = fmaxf(mx0, fmaxf(S[nt][0], S[nt][1]));
            mx1 = fmaxf(mx1, fmaxf(S[nt][2], S[nt][3]));
        }
        mx0 = fmaxf(mx0, __shfl_xor_sync(0xffffffffu, mx0, 1));
        mx0 = fmaxf(mx0, __shfl_xor_sync(0xffffffffu, mx0, 2));
        mx1 = fmaxf(mx1, __shfl_xor_sync(0xffffffffu, mx1, 1));
        mx1 = fmaxf(mx1, __shfl_xor_sync(0xffffffffu, mx1, 2));
        float mn0 = fmaxf(m0, mx0), mn1 = fmaxf(m1, mx1);
        float cf0 = __expf(scale * (m0 - mn0));
        float cf1 = __expf(scale * (m1 - mn1));
        m0 = mn0; m1 = mn1;
        float bb0 = -scale * mn0, bb1 = -scale * mn1;
        float rs0 = 0.f, rs1 = 0.f;
#pragma unroll
        for (int nt = 0; nt < 8; ++nt) {
            S[nt][0] = __expf(fmaf(S[nt][0], scale, bb0));
            S[nt][1] = __expf(fmaf(S[nt][1], scale, bb0));
            S[nt][2] = __expf(fmaf(S[nt][2], scale, bb1));
            S[nt][3] = __expf(fmaf(S[nt][3], scale, bb1));
            rs0 += S[nt][0] + S[nt][1];
            rs1 += S[nt][2] + S[nt][3];
        }
        rs0 += __shfl_xor_sync(0xffffffffu, rs0, 1);
        rs0 += __shfl_xor_sync(0xffffffffu, rs0, 2);
        rs1 += __shfl_xor_sync(0xffffffffu, rs1, 1);
        rs1 += __shfl_xor_sync(0xffffffffu, rs1, 2);
        l0 = l0 * cf0 + rs0;
        l1 = l1 * cf1 + rs1;

#pragma unroll
        for (int nt = 0; nt < 16; ++nt) {
            Oacc[nt][0] *= cf0; Oacc[nt][1] *= cf0;
            Oacc[nt][2] *= cf1; Oacc[nt][3] *= cf1;
        }
        uint32_t pa[4][4];
#pragma unroll
        for (int t = 0; t < 4; ++t) {
            pa[t][0] = pack_f16x2(S[2 * t][0],     S[2 * t][1]);
            pa[t][1] = pack_f16x2(S[2 * t][2],     S[2 * t][3]);
            pa[t][2] = pack_f16x2(S[2 * t + 1][0], S[2 * t + 1][1]);
            pa[t][3] = pack_f16x2(S[2 * t + 1][2], S[2 * t + 1][3]);
        }

        // ---- PV (fp16 x fp16 -> fp32) ----
        const uint32_t vbase = st + AV_OFF;
#pragma unroll
        for (int t = 0; t < 4; ++t) {
            uint32_t rowoff = vbase + (uint32_t)((t * 16 + (lane & 15)) * SROW + (lane >> 4) * 16);
#pragma unroll
            for (int dp = 0; dp < 8; ++dp) {
                uint32_t vb[4];
                ldsm_x4_t(vb, rowoff + dp * 32);
                mma16816h(Oacc[2 * dp + 0], pa[t], vb[0], vb[1]);
                mma16816h(Oacc[2 * dp + 1], pa[t], vb[2], vb[3]);
            }
        }
        stage = (stage == 2) ? 0 : stage + 1;
    }

    // ---- epilogue: normalize, write single fp16 O ----
    float inv0 = 1.0f / l0, inv1 = 1.0f / l1;
    int r = wid * 16 + (lane >> 2);
    size_t g0 = (qrow0 + r) * HIDDEN + hoff;
    size_t g1 = g0 + 8 * HIDDEN;
#pragma unroll
    for (int nt = 0; nt < 16; ++nt) {
        int col = nt * 8 + 2 * (lane & 3);
        *(__half2*)&Oh[g0 + col] = __float22half2_rn(
            make_float2(Oacc[nt][0] * inv0, Oacc[nt][1] * inv0));
        *(__half2*)&Oh[g1 + col] = __float22half2_rn(
            make_float2(Oacc[nt][2] * inv1, Oacc[nt][3] * inv1));
    }
}

// =====================================================================
extern "C" void kernel_launch(void* const* d_in, const int* in_sizes, int n_in,
                              void* d_out, int out_size)
{
    const float* x  = (const float*)d_in[0];
    const float* wq = (const float*)d_in[1];
    const float* wk = (const float*)d_in[2];
    const float* wv = (const float*)d_in[3];
    const float* wo = (const float*)d_in[4];
    float* out = (float*)d_out;

    __half *xh, *xl, *oh, *qbh, *qbl, *kbh, *kbl, *vf;
    __half *wqf, *wkf, *wvf, *wof;
    cudaGetSymbolAddress((void**)&xh, g_xh);   cudaGetSymbolAddress((void**)&xl, g_xl);
    cudaGetSymbolAddress((void**)&oh, g_oh);
    cudaGetSymbolAddress((void**)&qbh, g_qbh); cudaGetSymbolAddress((void**)&qbl, g_qbl);
    cudaGetSymbolAddress((void**)&kbh, g_kbh); cudaGetSymbolAddress((void**)&kbl, g_kbl);
    cudaGetSymbolAddress((void**)&vf, g_vf);
    cudaGetSymbolAddress((void**)&wqf, g_wqf); cudaGetSymbolAddress((void**)&wkf, g_wkf);
    cudaGetSymbolAddress((void**)&wvf, g_wvf); cudaGetSymbolAddress((void**)&wof, g_wof);

    const int M = MROWS;   // 4096

    cvt_all<<<24576, 256>>>((const float4*)x, (const float4*)wq, (const float4*)wk,
                            (const float4*)wv, (const float4*)wo,
                            (__half2*)xh, (__half2*)xl,
                            (__half2*)wqf, (__half2*)wkf, (__half2*)wvf, (__half2*)wof);

    cudaFuncSetAttribute(gemm2, cudaFuncAttributeMaxDynamicSharedMemorySize, GEMM_SMEM);
    // fused QKV: z=0 -> Q (2-pass, h/l out), z=1 -> K (2-pass, h/l out),
    //            z=2 -> V (1-pass, single fp16 out)
    gemm2<<<dim3(HIDDEN / 128, M / 128, 3), 256, GEMM_SMEM>>>(
        xh, xl, wqf, wkf, wvf, qbh, qbl, kbh, kbl, vf, nullptr,
        /*onepass_mask=*/0b100, M, HIDDEN, HIDDEN);

    cudaFuncSetAttribute(attn_mma, cudaFuncAttributeMaxDynamicSharedMemorySize, ATTN_SMEM);
    attn_mma<<<dim3(BATCH * NHEADS, SEQ / QT), 256, ATTN_SMEM>>>(qbh, qbl, kbh, kbl, vf, oh);

    // output projection: 1-pass (O single fp16), fp32 out
    gemm2<<<dim3(HIDDEN / 128, M / 128, 1), 256, GEMM_SMEM>>>(
        oh, oh, wof, wof, wof, nullptr, nullptr, nullptr, nullptr, nullptr, out,
        /*onepass_mask=*/0b001, M, HIDDEN, HIDDEN);
}

// round 11
// speedup vs baseline: 3.9572x; 1.0043x over previous
#include <cuda_runtime.h>
#include <cuda_fp16.h>
#include <cstdint>

#define HIDDEN 2048
#define SEQ    2048
#define BATCH  2
#define NHEADS 16
#define HDIM   128
#define MROWS  (BATCH * SEQ)   // 4096

// ---------- scratch (all fp16) ----------
__device__ __half g_xh[MROWS * HIDDEN], g_xl[MROWS * HIDDEN];
__device__ __half g_oh[MROWS * HIDDEN];
__device__ __half g_qbh[MROWS * HIDDEN], g_qbl[MROWS * HIDDEN];
__device__ __half g_kbh[MROWS * HIDDEN], g_kbl[MROWS * HIDDEN];
__device__ __half g_vf[MROWS * HIDDEN];
__device__ __half g_wqf[HIDDEN * HIDDEN], g_wkf[HIDDEN * HIDDEN];
__device__ __half g_wvf[HIDDEN * HIDDEN], g_wof[HIDDEN * HIDDEN];

// ---------- PTX wrappers (sm_80/90-era, valid on compute_103) ----------
__device__ __forceinline__ uint32_t smem_u32(const void* p) {
    uint32_t a;
    asm("{ .reg .u64 t; cvta.to.shared.u64 t, %1; cvt.u32.u64 %0, t; }" : "=r"(a) : "l"(p));
    return a;
}
__device__ __forceinline__ void cp16(uint32_t sdst, const void* gsrc) {
    asm volatile("cp.async.cg.shared.global [%0], [%1], 16;" :: "r"(sdst), "l"(gsrc) : "memory");
}
#define CP_COMMIT() asm volatile("cp.async.commit_group;" ::: "memory")
#define CP_WAIT1()  asm volatile("cp.async.wait_group 1;" ::: "memory")
#define CP_WAIT2()  asm volatile("cp.async.wait_group 2;" ::: "memory")

__device__ __forceinline__ void ldsm_x4(uint32_t (&r)[4], uint32_t addr) {
    asm volatile("ldmatrix.sync.aligned.m8n8.x4.shared.b16 {%0,%1,%2,%3}, [%4];"
                 : "=r"(r[0]), "=r"(r[1]), "=r"(r[2]), "=r"(r[3]) : "r"(addr));
}
__device__ __forceinline__ void ldsm_x4_t(uint32_t (&r)[4], uint32_t addr) {
    asm volatile("ldmatrix.sync.aligned.m8n8.x4.trans.shared.b16 {%0,%1,%2,%3}, [%4];"
                 : "=r"(r[0]), "=r"(r[1]), "=r"(r[2]), "=r"(r[3]) : "r"(addr));
}
__device__ __forceinline__ void mma16816h(float (&d)[4], const uint32_t (&a)[4],
                                          uint32_t b0, uint32_t b1) {
    asm volatile(
        "mma.sync.aligned.m16n8k16.row.col.f32.f16.f16.f32 "
        "{%0,%1,%2,%3}, {%4,%5,%6,%7}, {%8,%9}, {%0,%1,%2,%3};"
        : "+f"(d[0]), "+f"(d[1]), "+f"(d[2]), "+f"(d[3])
        : "r"(a[0]), "r"(a[1]), "r"(a[2]), "r"(a[3]), "r"(b0), "r"(b1));
}
__device__ __forceinline__ uint32_t pack_f16x2(float lo, float hi) {
    __half2 h = __float22half2_rn(make_float2(lo, hi));
    return *(uint32_t*)&h;
}

// ---------- fused fp32 -> fp16 conversions ----------
__global__ __launch_bounds__(256)
void cvt_all(const float4* __restrict__ x,  const float4* __restrict__ wq,
             const float4* __restrict__ wk, const float4* __restrict__ wv,
             const float4* __restrict__ wo,
             __half2* xh, __half2* xl,
             __half2* wqf, __half2* wkf, __half2* wvf, __half2* wof)
{
    int bid = blockIdx.x;
    if (bid < 8192) {
        size_t i = (size_t)bid * 256 + threadIdx.x;
        float4 v = x[i];
        __half hx = __float2half_rn(v.x), hy = __float2half_rn(v.y);
        __half hz = __float2half_rn(v.z), hw = __float2half_rn(v.w);
        xh[2 * i]     = __halves2half2(hx, hy);
        xh[2 * i + 1] = __halves2half2(hz, hw);
        xl[2 * i]     = __halves2half2(__float2half_rn(v.x - __half2float(hx)),
                                       __float2half_rn(v.y - __half2float(hy)));
        xl[2 * i + 1] = __halves2half2(__float2half_rn(v.z - __half2float(hz)),
                                       __float2half_rn(v.w - __half2float(hw)));
        return;
    }
    const float4* src; __half2* dst; int base;
    if      (bid < 12288) { src = wq; dst = wqf; base = bid - 8192; }
    else if (bid < 16384) { src = wk; dst = wkf; base = bid - 12288; }
    else if (bid < 20480) { src = wv; dst = wvf; base = bid - 16384; }
    else                  { src = wo; dst = wof; base = bid - 20480; }
    size_t i = (size_t)base * 256 + threadIdx.x;
    float4 v = src[i];
    dst[2 * i]     = __float22half2_rn(make_float2(v.x, v.y));
    dst[2 * i + 1] = __float22half2_rn(make_float2(v.z, v.w));
}

// =====================================================================
// fp16 HMMA GEMM: C = (Ah [+ Al]) @ B^T.  onepass_mask bit z => skip Al.
// 128x128 CTA tile, 8 warps (4m x 2n), BK=32, 64B rows + XOR swizzle.
// GROUP-PAIRED pipeline: 4 stages = 2 groups of 2 chunks.
// Per group: sync -> load G(g+1) -> commit -> wait_group 1 -> compute 2 chunks.
// One barrier per 2 chunks (32 total).
// =====================================================================
#define BK       32
#define NKCH     (HIDDEN / BK)          // 64
#define NGRP     (NKCH / 2)             // 32
#define ROWB     64
#define TILE_B   (128 * ROWB)           // 8192
#define STAGE_B  (3 * TILE_B)           // 24576: Ah Al B
#define GEMM_SMEM (4 * STAGE_B)         // 98304

__global__ __launch_bounds__(256, 2)
void gemm2(const __half* __restrict__ Ah, const __half* __restrict__ Al,
           const __half* __restrict__ B0, const __half* __restrict__ B1,
           const __half* __restrict__ B2,
           __half* __restrict__ Ch0, __half* __restrict__ Cl0,
           __half* __restrict__ Ch1, __half* __restrict__ Cl1,
           __half* __restrict__ Cf2,
           float* __restrict__ C,
           int onepass_mask,
           int M, int N, int K)
{
    extern __shared__ __align__(128) char smem[];
    const uint32_t sbase = smem_u32(smem);
    const int tid  = threadIdx.x;
    const int wid  = tid >> 5;
    const int lane = tid & 31;
    const int wm   = wid & 3;
    const int wn   = wid >> 2;
    const int z    = blockIdx.z;
    const bool two = !((onepass_mask >> z) & 1);
    const size_t brow = (size_t)blockIdx.y * 128;
    const size_t bcol = (size_t)blockIdx.x * 128;

    const __half* Bsel = (z == 0) ? B0 : (z == 1) ? B1 : B2;

    const int row = tid >> 1;
    const int sp  = (tid & 1) * 2;
    const int wmsk = (row >> 1) & 3;
    const uint32_t soff0 = (uint32_t)(row * ROWB + ((sp    ) ^ wmsk) * 16);
    const uint32_t soff1 = (uint32_t)(row * ROWB + ((sp + 1) ^ wmsk) * 16);

    const size_t Kb = (size_t)K * 2;
    const char* pAh = (const char*)Ah   + (brow + row) * Kb + sp * 16;
    const char* pAl = (const char*)Al   + (brow + row) * Kb + sp * 16;
    const char* pB  = (const char*)Bsel + (bcol + row) * Kb + sp * 16;

#define LOAD_CHUNK(c, s) do {                                    \
        uint32_t sb_ = sbase + (uint32_t)(s) * STAGE_B;          \
        size_t g_ = (size_t)(c) * 64;                            \
        cp16(sb_ + 0 * TILE_B + soff0, pAh + g_);                \
        cp16(sb_ + 0 * TILE_B + soff1, pAh + g_ + 16);           \
        if (two) {                                               \
            cp16(sb_ + 1 * TILE_B + soff0, pAl + g_);            \
            cp16(sb_ + 1 * TILE_B + soff1, pAl + g_ + 16);       \
        }                                                        \
        cp16(sb_ + 2 * TILE_B + soff0, pB  + g_);                \
        cp16(sb_ + 2 * TILE_B + soff1, pB  + g_ + 16);           \
    } while (0)

    const int rA    = wm * 32 + (lane & 15);
    const int aSeg  = lane >> 4;
    const int maskA = (rA >> 1) & 3;
    const int rB    = wn * 64 + ((lane >> 4) << 3) + (lane & 7);
    const int bSeg  = (lane >> 3) & 1;
    const int maskB = (rB >> 1) & 3;

    float acc[2][8][4];
#pragma unroll
    for (int mt = 0; mt < 2; ++mt)
#pragma unroll
        for (int nt = 0; nt < 8; ++nt)
#pragma unroll
            for (int q = 0; q < 4; ++q) acc[mt][nt][q] = 0.f;

    // prologue: group 0 only
    LOAD_CHUNK(0, 0);
    LOAD_CHUNK(1, 1);
    CP_COMMIT();

    for (int g = 0; g < NGRP; ++g) {
        __syncthreads();                 // all warps done with group g-1
        if (g + 1 < NGRP) {
            // load group g+1 into the pair that held group g-1
            LOAD_CHUNK(2 * g + 2, (2 * g + 2) & 3);
            LOAD_CHUNK(2 * g + 3, (2 * g + 3) & 3);
        }
        CP_COMMIT();
        CP_WAIT1();                      // group g's data complete

        // compute the two chunks of group g
#pragma unroll
        for (int u = 0; u < 2; ++u) {
            const uint32_t sb = sbase + (uint32_t)((2 * g + u) & 3) * STAGE_B;

#pragma unroll
            for (int k16 = 0; k16 < 2; ++k16) {
                uint32_t ah[2][4];
#pragma unroll
                for (int mt = 0; mt < 2; ++mt) {
                    uint32_t byteoff = (uint32_t)((rA + mt * 16) * ROWB +
                                                  ((2 * k16 + aSeg) ^ maskA) * 16);
                    ldsm_x4(ah[mt], sb + 0 * TILE_B + byteoff);
                }
                uint32_t bh[4][4];
#pragma unroll
                for (int np = 0; np < 4; ++np) {
                    uint32_t byteoff = (uint32_t)((rB + np * 16) * ROWB +
                                                  ((2 * k16 + bSeg) ^ maskB) * 16);
                    ldsm_x4(bh[np], sb + 2 * TILE_B + byteoff);
                }
                // pass 1: Ah * B
#pragma unroll
                for (int np = 0; np < 4; ++np)
#pragma unroll
                    for (int mt = 0; mt < 2; ++mt) {
                        mma16816h(acc[mt][2 * np + 0], ah[mt], bh[np][0], bh[np][1]);
                        mma16816h(acc[mt][2 * np + 1], ah[mt], bh[np][2], bh[np][3]);
                    }
                // pass 2: Al * B (skipped for one-pass outputs)
                if (two) {
                    uint32_t al[2][4];
#pragma unroll
                    for (int mt = 0; mt < 2; ++mt) {
                        uint32_t byteoff = (uint32_t)((rA + mt * 16) * ROWB +
                                                      ((2 * k16 + aSeg) ^ maskA) * 16);
                        ldsm_x4(al[mt], sb + 1 * TILE_B + byteoff);
                    }
#pragma unroll
                    for (int np = 0; np < 4; ++np)
#pragma unroll
                        for (int mt = 0; mt < 2; ++mt) {
                            mma16816h(acc[mt][2 * np + 0], al[mt], bh[np][0], bh[np][1]);
                            mma16816h(acc[mt][2 * np + 1], al[mt], bh[np][2], bh[np][3]);
                        }
                }
            }
        }
    }

    __half* Ch = (z == 0) ? Ch0 : Ch1;
    __half* Cl = (z == 0) ? Cl0 : Cl1;
#pragma unroll
    for (int mt = 0; mt < 2; ++mt) {
        size_t r0 = brow + wm * 32 + mt * 16 + (lane >> 2);
#pragma unroll
        for (int nt = 0; nt < 8; ++nt) {
            size_t col = bcol + wn * 64 + nt * 8 + 2 * (lane & 3);
            if (C) {
                *(float2*)&C[r0 * (size_t)N + col]       = make_float2(acc[mt][nt][0], acc[mt][nt][1]);
                *(float2*)&C[(r0 + 8) * (size_t)N + col] = make_float2(acc[mt][nt][2], acc[mt][nt][3]);
            } else if (z == 2) {
#pragma unroll
                for (int hf = 0; hf < 2; ++hf) {
                    size_t idx = (r0 + 8 * hf) * (size_t)N + col;
                    *(__half2*)&Cf2[idx] = __float22half2_rn(
                        make_float2(acc[mt][nt][2 * hf], acc[mt][nt][2 * hf + 1]));
                }
            } else {
#pragma unroll
                for (int hf = 0; hf < 2; ++hf) {
                    float v0 = acc[mt][nt][2 * hf + 0];
                    float v1 = acc[mt][nt][2 * hf + 1];
                    __half h0 = __float2half_rn(v0);
                    __half h1 = __float2half_rn(v1);
                    size_t idx = (r0 + 8 * hf) * (size_t)N + col;
                    *(__half2*)&Ch[idx] = __halves2half2(h0, h1);
                    *(__half2*)&Cl[idx] = __halves2half2(
                        __float2half_rn(v0 - __half2float(h0)),
                        __float2half_rn(v1 - __half2float(h1)));
                }
            }
        }
    }
}

// =====================================================================
// FlashAttention-2 on fp16 HMMA. Scores: 3-pass hi/lo fp16 (near-exact).
// PV: fp16 P and V, single pass. 3-stage KV pipeline, one sync per tile.
// O written as single fp16 (Oh only).
// =====================================================================
#define QT        128
#define SROW      272
#define AQL_OFF   34816
#define AST_OFF   69632
#define AST_SZ    52224
#define AKL_OFF   17408
#define AV_OFF    34816
#define ATTN_SMEM 226304
#define NKT       (SEQ / 64)   // 32

__global__ __launch_bounds__(256, 1)
void attn_mma(const __half* __restrict__ Qh, const __half* __restrict__ Ql,
              const __half* __restrict__ Kh, const __half* __restrict__ Kl,
              const __half* __restrict__ Vf,
              __half* __restrict__ Oh)
{
    extern __shared__ __align__(128) char smem[];
    const uint32_t sb = smem_u32(smem);
    const int tid  = threadIdx.x;
    const int wid  = tid >> 5;
    const int lane = tid & 31;
    const int b    = blockIdx.x >> 4;
    const int h    = blockIdx.x & 15;
    const int qt   = blockIdx.y;

    const float scale = 0.08838834764831843f;   // 1/sqrt(128)
    const size_t hoff  = (size_t)h * HDIM;
    const size_t qrow0 = (size_t)b * SEQ + (size_t)qt * QT;
    const size_t krow0 = (size_t)b * SEQ;

#pragma unroll
    for (int it = 0; it < 8; ++it) {
        int idx = it * 256 + tid;
        int r   = idx >> 4;
        int ch  = idx & 15;
        size_t g = ((qrow0 + r) * HIDDEN + hoff + ch * 8) * 2;
        uint32_t d = sb + (uint32_t)(r * SROW + ch * 16);
        cp16(d,           (const char*)Qh + g);
        cp16(d + AQL_OFF, (const char*)Ql + g);
    }
#define LOAD_KV(c, s) do {                                                     \
        uint32_t st_ = sb + AST_OFF + (uint32_t)(s) * AST_SZ;                  \
        _Pragma("unroll")                                                      \
        for (int it_ = 0; it_ < 4; ++it_) {                                    \
            int idx_ = it_ * 256 + tid;                                        \
            int r_  = idx_ >> 4;                                               \
            int ch_ = idx_ & 15;                                               \
            size_t g_ = ((krow0 + (size_t)(c) * 64 + r_) * HIDDEN + hoff + ch_ * 8) * 2; \
            uint32_t d_ = st_ + (uint32_t)(r_ * SROW + ch_ * 16);              \
            cp16(d_,           (const char*)Kh + g_);                          \
            cp16(d_ + AKL_OFF, (const char*)Kl + g_);                          \
            cp16(d_ + AV_OFF,  (const char*)Vf + g_);                          \
        }                                                                      \
    } while (0)

    LOAD_KV(0, 0); CP_COMMIT();
    LOAD_KV(1, 1); CP_COMMIT();
    CP_WAIT1();
    __syncthreads();

    const int arow = lane & 15;
    const int aseg = lane >> 4;
    const uint32_t qbase = sb + (uint32_t)((wid * 16 + arow) * SROW + aseg * 16);
    uint32_t qh[8][4];
#pragma unroll
    for (int ks = 0; ks < 8; ++ks) ldsm_x4(qh[ks], qbase + ks * 32);
    const uint32_t qlbase = qbase + AQL_OFF;

    float Oacc[16][4];
#pragma unroll
    for (int nt = 0; nt < 16; ++nt)
#pragma unroll
        for (int q = 0; q < 4; ++q) Oacc[nt][q] = 0.f;
    float m0 = -1e30f, m1 = -1e30f, l0 = 0.f, l1 = 0.f;

    const int brow = ((lane >> 4) << 3) + (lane & 7);
    const int bseg = (lane >> 3) & 1;

    int stage = 0;
    for (int kt = 0; kt < NKT; ++kt) {
        __syncthreads();
        if (kt + 2 < NKT) {
            int s2 = stage + 2; if (s2 >= 3) s2 -= 3;
            LOAD_KV(kt + 2, s2);
        }
        CP_COMMIT();
        CP_WAIT2();

        const uint32_t st = sb + AST_OFF + (uint32_t)stage * AST_SZ;

        float S[8][4];
#pragma unroll
        for (int nt = 0; nt < 8; ++nt)
#pragma unroll
            for (int q = 0; q < 4; ++q) S[nt][q] = 0.f;

#pragma unroll
        for (int ks = 0; ks < 8; ++ks) {
            uint32_t koff = (uint32_t)(brow * SROW + ks * 32 + bseg * 16);
            uint32_t kh4[4][4];
#pragma unroll
            for (int p = 0; p < 4; ++p) ldsm_x4(kh4[p], st + p * (16 * SROW) + koff);
#pragma unroll
            for (int p = 0; p < 4; ++p) {
                mma16816h(S[2 * p + 0], qh[ks], kh4[p][0], kh4[p][1]);
                mma16816h(S[2 * p + 1], qh[ks], kh4[p][2], kh4[p][3]);
            }
            uint32_t ql4[4];
            ldsm_x4(ql4, qlbase + ks * 32);
#pragma unroll
            for (int p = 0; p < 4; ++p) {
                mma16816h(S[2 * p + 0], ql4, kh4[p][0], kh4[p][1]);
                mma16816h(S[2 * p + 1], ql4, kh4[p][2], kh4[p][3]);
            }
#pragma unroll
            for (int p = 0; p < 4; ++p) {
                uint32_t kl4[4];
                ldsm_x4(kl4, st + AKL_OFF + p * (16 * SROW) + koff);
                mma16816h(S[2 * p + 0], qh[ks], kl4[0], kl4[1]);
                mma16816h(S[2 * p + 1], qh[ks], kl4[2], kl4[3]);
            }
        }

        // ---- online softmax ----
        float mx0 = -1e30f, mx1 = -1e30f;
#pragma unroll
        for (int nt = 0; nt < 8; ++nt) {
            mx0 = fmaxf(mx0, fmaxf(S[nt][0], S[nt][1]));
            mx1 = fmaxf(mx1, fmaxf(S[nt][2], S[nt][3]));
        }
        mx0 = fmaxf(mx0, __shfl_xor_sync(0xffffffffu, mx0, 1));
        mx0 = fmaxf(mx0, __shfl_xor_sync(0xffffffffu, mx0, 2));
        mx1 = fmaxf(mx1, __shfl_xor_sync(0xffffffffu, mx1, 1));
        mx1 = fmaxf(mx1, __shfl_xor_sync(0xffffffffu, mx1, 2));
        float mn0 = fmaxf(m0, mx0), mn1 = fmaxf(m1, mx1);
        float cf0 = __expf(scale * (m0 - mn0));
        float cf1 = __expf(scale * (m1 - mn1));
        m0 = mn0; m1 = mn1;
        float bb0 = -scale * mn0, bb1 = -scale * mn1;
        float rs0 = 0.f, rs1 = 0.f;
#pragma unroll
        for (int nt = 0; nt < 8; ++nt) {
            S[nt][0] = __expf(fmaf(S[nt][0], scale, bb0));
            S[nt][1] = __expf(fmaf(S[nt][1], scale, bb0));
            S[nt][2] = __expf(fmaf(S[nt][2], scale, bb1));
            S[nt][3] = __expf(fmaf(S[nt][3], scale, bb1));
            rs0 += S[nt][0] + S[nt][1];
            rs1 += S[nt][2] + S[nt][3];
        }
        rs0 += __shfl_xor_sync(0xffffffffu, rs0, 1);
        rs0 += __shfl_xor_sync(0xffffffffu, rs0, 2);
        rs1 += __shfl_xor_sync(0xffffffffu, rs1, 1);
        rs1 += __shfl_xor_sync(0xffffffffu, rs1, 2);
        l0 = l0 * cf0 + rs0;
        l1 = l1 * cf1 + rs1;

#pragma unroll
        for (int nt = 0; nt < 16; ++nt) {
            Oacc[nt][0] *= cf0; Oacc[nt][1] *= cf0;
            Oacc[nt][2] *= cf1; Oacc[nt][3] *= cf1;
        }
        uint32_t pa[4][4];
#pragma unroll
        for (int t = 0; t < 4; ++t) {
            pa[t][0] = pack_f16x2(S[2 * t][0],     S[2 * t][1]);
            pa[t][1] = pack_f16x2(S[2 * t][2],     S[2 * t][3]);
            pa[t][2] = pack_f16x2(S[2 * t + 1][0], S[2 * t + 1][1]);
            pa[t][3] = pack_f16x2(S[2 * t + 1][2], S[2 * t + 1][3]);
        }

        // ---- PV (fp16 x fp16 -> fp32) ----
        const uint32_t vbase = st + AV_OFF;
#pragma unroll
        for (int t = 0; t < 4; ++t) {
            uint32_t rowoff = vbase + (uint32_t)((t * 16 + (lane & 15)) * SROW + (lane >> 4) * 16);
#pragma unroll
            for (int dp = 0; dp < 8; ++dp) {
                uint32_t vb[4];
                ldsm_x4_t(vb, rowoff + dp * 32);
                mma16816h(Oacc[2 * dp + 0], pa[t], vb[0], vb[1]);
                mma16816h(Oacc[2 * dp + 1], pa[t], vb[2], vb[3]);
            }
        }
        stage = (stage == 2) ? 0 : stage + 1;
    }

    // ---- epilogue: normalize, write single fp16 O ----
    float inv0 = 1.0f / l0, inv1 = 1.0f / l1;
    int r = wid * 16 + (lane >> 2);
    size_t g0 = (qrow0 + r) * HIDDEN + hoff;
    size_t g1 = g0 + 8 * HIDDEN;
#pragma unroll
    for (int nt = 0; nt < 16; ++nt) {
        int col = nt * 8 + 2 * (lane & 3);
        *(__half2*)&Oh[g0 + col] = __float22half2_rn(
            make_float2(Oacc[nt][0] * inv0, Oacc[nt][1] * inv0));
        *(__half2*)&Oh[g1 + col] = __float22half2_rn(
            make_float2(Oacc[nt][2] * inv1, Oacc[nt][3] * inv1));
    }
}

// =====================================================================
extern "C" void kernel_launch(void* const* d_in, const int* in_sizes, int n_in,
                              void* d_out, int out_size)
{
    const float* x  = (const float*)d_in[0];
    const float* wq = (const float*)d_in[1];
    const float* wk = (const float*)d_in[2];
    const float* wv = (const float*)d_in[3];
    const float* wo = (const float*)d_in[4];
    float* out = (float*)d_out;

    __half *xh, *xl, *oh, *qbh, *qbl, *kbh, *kbl, *vf;
    __half *wqf, *wkf, *wvf, *wof;
    cudaGetSymbolAddress((void**)&xh, g_xh);   cudaGetSymbolAddress((void**)&xl, g_xl);
    cudaGetSymbolAddress((void**)&oh, g_oh);
    cudaGetSymbolAddress((void**)&qbh, g_qbh); cudaGetSymbolAddress((void**)&qbl, g_qbl);
    cudaGetSymbolAddress((void**)&kbh, g_kbh); cudaGetSymbolAddress((void**)&kbl, g_kbl);
    cudaGetSymbolAddress((void**)&vf, g_vf);
    cudaGetSymbolAddress((void**)&wqf, g_wqf); cudaGetSymbolAddress((void**)&wkf, g_wkf);
    cudaGetSymbolAddress((void**)&wvf, g_wvf); cudaGetSymbolAddress((void**)&wof, g_wof);

    const int M = MROWS;   // 4096

    cvt_all<<<24576, 256>>>((const float4*)x, (const float4*)wq, (const float4*)wk,
                            (const float4*)wv, (const float4*)wo,
                            (__half2*)xh, (__half2*)xl,
                            (__half2*)wqf, (__half2*)wkf, (__half2*)wvf, (__half2*)wof);

    cudaFuncSetAttribute(gemm2, cudaFuncAttributeMaxDynamicSharedMemorySize, GEMM_SMEM);
    // fused QKV: z=0 -> Q (2-pass, h/l out), z=1 -> K (2-pass, h/l out),
    //            z=2 -> V (1-pass, single fp16 out)
    gemm2<<<dim3(HIDDEN / 128, M / 128, 3), 256, GEMM_SMEM>>>(
        xh, xl, wqf, wkf, wvf, qbh, qbl, kbh, kbl, vf, nullptr,
        /*onepass_mask=*/0b100, M, HIDDEN, HIDDEN);

    cudaFuncSetAttribute(attn_mma, cudaFuncAttributeMaxDynamicSharedMemorySize, ATTN_SMEM);
    attn_mma<<<dim3(BATCH * NHEADS, SEQ / QT), 256, ATTN_SMEM>>>(qbh, qbl, kbh, kbl, vf, oh);

    // output projection: 1-pass (O single fp16), fp32 out
    gemm2<<<dim3(HIDDEN / 128, M / 128, 1), 256, GEMM_SMEM>>>(
        oh, oh, wof, wof, wof, nullptr, nullptr, nullptr, nullptr, nullptr, out,
        /*onepass_mask=*/0b001, M, HIDDEN, HIDDEN);
}